// round 1
// baseline (speedup 1.0000x reference)
#include <cuda_runtime.h>
#include <math.h>
#include <stdint.h>

#define N_NODES 50000
#define N_EDGES 400000
#define D 128
#define H 256
#define EATTR 64
#define XW 160      /* D + SPLIT */
#define LN_EPS 1e-5f
#define SLOPE 0.01f

// ---------------- device scratch (no allocs allowed) ----------------
__device__ float g_P0[(size_t)N_NODES * H];   // xn @ d2t_w1_top
__device__ float g_P1[(size_t)N_NODES * H];   // xn @ t2d_w1_top
__device__ float g_acol[N_NODES];
__device__ float g_arow[N_NODES];
__device__ float g_expv[N_EDGES];             // logits, then exp(logit-max)
__device__ int   g_elist0[N_EDGES];
__device__ int   g_elist1[N_EDGES];
__device__ float g_flow[(size_t)N_NODES * 256];
__device__ float g_dirmax[2];
__device__ float g_dirsum[2];
__device__ int   g_ecnt[2];

// ---------------- helpers ----------------
__device__ __forceinline__ void barSync(int id) {
    asm volatile("bar.sync %0, %1;" :: "r"(id), "r"(128) : "memory");
}

__device__ __forceinline__ void atomicMaxF(float* addr, float val) {
    int* ai = (int*)addr;
    int old = *ai;
    while (__int_as_float(old) < val) {
        int assumed = old;
        old = atomicCAS(ai, assumed, __float_as_int(val));
        if (old == assumed) break;
    }
}

// reduce NV independent values across a 128-thread unit (4 warps)
template<int NV>
__device__ __forceinline__ void ureduce(float* v, float* red, int wu, int lane, int barid) {
    #pragma unroll
    for (int o = 16; o; o >>= 1) {
        #pragma unroll
        for (int k = 0; k < NV; k++) v[k] += __shfl_xor_sync(0xffffffffu, v[k], o);
    }
    if (lane == 0) {
        #pragma unroll
        for (int k = 0; k < NV; k++) red[wu * NV + k] = v[k];
    }
    barSync(barid);
    #pragma unroll
    for (int k = 0; k < NV; k++)
        v[k] = red[k] + red[NV + k] + red[2 * NV + k] + red[3 * NV + k];
    barSync(barid);
}

// ---------------- kernels ----------------
__global__ void k_init() {
    size_t i = (size_t)blockIdx.x * blockDim.x + threadIdx.x;
    size_t n4 = (size_t)N_NODES * 256 / 4;
    if (i < n4) reinterpret_cast<float4*>(g_flow)[i] = make_float4(0.f, 0.f, 0.f, 0.f);
    if (i == 0) {
        g_dirmax[0] = -INFINITY; g_dirmax[1] = -INFINITY;
        g_dirsum[0] = 0.f; g_dirsum[1] = 0.f;
        g_ecnt[0] = 0; g_ecnt[1] = 0;
    }
}

// per-node attention dots: a_col = xn . w_att[0:128], a_row = xn . w_att[128:256]
__global__ void k_att_pre(const float* __restrict__ x, const float* __restrict__ w_att) {
    int warp = (blockIdx.x * blockDim.x + threadIdx.x) >> 5;
    int lane = threadIdx.x & 31;
    if (warp >= N_NODES) return;
    const float* xr = x + (size_t)warp * XW;
    float s0 = 0.f, s1 = 0.f;
    for (int i = lane; i < 128; i += 32) {
        float v = xr[i];
        s0 += v * w_att[i];
        s1 += v * w_att[128 + i];
    }
    #pragma unroll
    for (int o = 16; o; o >>= 1) {
        s0 += __shfl_xor_sync(0xffffffffu, s0, o);
        s1 += __shfl_xor_sync(0xffffffffu, s1, o);
    }
    if (lane == 0) { g_acol[warp] = s0; g_arow[warp] = s1; }
}

// per-node P = xn @ W1_top for both directions (NB=16 nodes/block)
__global__ void k_node_pre(const float* __restrict__ x,
                           const float* __restrict__ w0,   // d2t_w1 (192x256)
                           const float* __restrict__ w1) { // t2d_w1
    __shared__ float xs[16 * 128];
    int nb = blockIdx.x * 16;
    for (int idx = threadIdx.x; idx < 16 * 128; idx += 256) {
        int nn = idx >> 7, i = idx & 127;
        int node = nb + nn;
        xs[idx] = (node < N_NODES) ? x[(size_t)node * XW + i] : 0.f;
    }
    __syncthreads();
    int j = threadIdx.x; // 0..255
    for (int d = 0; d < 2; d++) {
        const float* W = d ? w1 : w0;   // top 128 rows
        float* P = d ? g_P1 : g_P0;
        float acc[16];
        #pragma unroll
        for (int n = 0; n < 16; n++) acc[n] = 0.f;
        for (int i = 0; i < 128; i += 4) {
            float wv0 = __ldg(&W[(size_t)(i + 0) * H + j]);
            float wv1 = __ldg(&W[(size_t)(i + 1) * H + j]);
            float wv2 = __ldg(&W[(size_t)(i + 2) * H + j]);
            float wv3 = __ldg(&W[(size_t)(i + 3) * H + j]);
            #pragma unroll
            for (int n = 0; n < 16; n++) {
                float4 xv = *reinterpret_cast<float4*>(&xs[n * 128 + i]);
                acc[n] += xv.x * wv0 + xv.y * wv1 + xv.z * wv2 + xv.w * wv3;
            }
        }
        #pragma unroll
        for (int n = 0; n < 16; n++) {
            int node = nb + n;
            if (node < N_NODES) P[(size_t)node * H + j] = acc[n];
        }
    }
}

// per-edge logit + per-direction max
__global__ void k_logit_max(const int* __restrict__ ei, const float* __restrict__ b_att) {
    int e = blockIdx.x * blockDim.x + threadIdx.x;
    float m0 = -INFINITY, m1 = -INFINITY;
    if (e < N_EDGES) {
        int r = ei[e], c = ei[N_EDGES + e];
        float z = g_acol[c] + g_arow[r] + b_att[0];
        float lg = z > 0.f ? z : SLOPE * z;
        g_expv[e] = lg;
        if (r < c) m0 = lg; else if (r > c) m1 = lg;
    }
    #pragma unroll
    for (int o = 16; o; o >>= 1) {
        m0 = fmaxf(m0, __shfl_xor_sync(0xffffffffu, m0, o));
        m1 = fmaxf(m1, __shfl_xor_sync(0xffffffffu, m1, o));
    }
    __shared__ float s0[8], s1[8];
    int w = threadIdx.x >> 5, l = threadIdx.x & 31;
    if (l == 0) { s0[w] = m0; s1[w] = m1; }
    __syncthreads();
    if (threadIdx.x == 0) {
        float a = -INFINITY, b = -INFINITY;
        for (int k = 0; k < 8; k++) { a = fmaxf(a, s0[k]); b = fmaxf(b, s1[k]); }
        atomicMaxF(&g_dirmax[0], a);
        atomicMaxF(&g_dirmax[1], b);
    }
}

// exp + per-direction sum + compacted edge lists
__global__ void k_sumexp(const int* __restrict__ ei) {
    __shared__ int c0, c1, base0, base1;
    __shared__ float rs0[8], rs1[8];
    if (threadIdx.x == 0) { c0 = 0; c1 = 0; }
    __syncthreads();
    int e = blockIdx.x * blockDim.x + threadIdx.x;
    int dir = -1, pos = 0;
    float ex = 0.f;
    if (e < N_EDGES) {
        int r = ei[e], c = ei[N_EDGES + e];
        if (r < c) dir = 0; else if (r > c) dir = 1;
        if (dir >= 0) {
            ex = expf(g_expv[e] - g_dirmax[dir]);
            pos = atomicAdd(dir ? &c1 : &c0, 1);
        }
        g_expv[e] = (dir >= 0) ? ex : 0.f;
    }
    float v0 = (dir == 0) ? ex : 0.f;
    float v1 = (dir == 1) ? ex : 0.f;
    #pragma unroll
    for (int o = 16; o; o >>= 1) {
        v0 += __shfl_xor_sync(0xffffffffu, v0, o);
        v1 += __shfl_xor_sync(0xffffffffu, v1, o);
    }
    int w = threadIdx.x >> 5, l = threadIdx.x & 31;
    if (l == 0) { rs0[w] = v0; rs1[w] = v1; }
    __syncthreads();
    if (threadIdx.x == 0) {
        float t0 = 0.f, t1 = 0.f;
        for (int k = 0; k < 8; k++) { t0 += rs0[k]; t1 += rs1[k]; }
        if (t0 != 0.f) atomicAdd(&g_dirsum[0], t0);
        if (t1 != 0.f) atomicAdd(&g_dirsum[1], t1);
        base0 = c0 ? atomicAdd(&g_ecnt[0], c0) : 0;
        base1 = c1 ? atomicAdd(&g_ecnt[1], c1) : 0;
    }
    __syncthreads();
    if (dir == 0) g_elist0[base0 + pos] = e;
    else if (dir == 1) g_elist1[base1 + pos] = e;
}

// ---------------- fused edge MLP ----------------
// SMEM float layout:
//   [0)       wbot 64*256 = 16384
//   [16384)   w2   256*128 = 32768
//   [49152)   b1 256, g1 256, be1 256
//   [49920)   b2 128, g2 128, be2 128
//   [50304)   4 units * 1312: eas_t 256 | h1s_t 1024 | red 32
#define EDGE_SMEM_FLOATS (50304 + 4 * 1312)

__global__ void __launch_bounds__(512, 1) k_edge(
    int dir,
    const int* __restrict__ ei, const float* __restrict__ eattr,
    const float* __restrict__ w1full,
    const float* __restrict__ b1, const float* __restrict__ g1, const float* __restrict__ be1,
    const float* __restrict__ w2, const float* __restrict__ b2,
    const float* __restrict__ g2, const float* __restrict__ be2)
{
    extern __shared__ float sm[];
    float* wbot = sm;
    float* w2s  = sm + 16384;
    float* b1s  = sm + 49152;
    float* g1s  = sm + 49408;
    float* be1s = sm + 49664;
    float* b2s  = sm + 49920;
    float* g2s  = sm + 50048;
    float* be2s = sm + 50176;

    const float* wbg = w1full + 128 * H;
    for (int idx = threadIdx.x; idx < 16384; idx += 512) wbot[idx] = wbg[idx];
    for (int idx = threadIdx.x; idx < 32768; idx += 512) w2s[idx] = w2[idx];
    if (threadIdx.x < 256) {
        b1s[threadIdx.x]  = b1[threadIdx.x];
        g1s[threadIdx.x]  = g1[threadIdx.x];
        be1s[threadIdx.x] = be1[threadIdx.x];
    }
    if (threadIdx.x < 128) {
        b2s[threadIdx.x]  = b2[threadIdx.x];
        g2s[threadIdx.x]  = g2[threadIdx.x];
        be2s[threadIdx.x] = be2[threadIdx.x];
    }
    __syncthreads();

    int unit = threadIdx.x >> 7;
    int t    = threadIdx.x & 127;
    int wu   = t >> 5;
    int lane = threadIdx.x & 31;
    int barid = unit + 1;
    float* U   = sm + 50304 + unit * 1312;
    float* eas = U;
    float* h1s = U + 256;
    float* red = U + 1280;

    const int*   elist = dir ? g_elist1 : g_elist0;
    const float* P     = dir ? g_P1 : g_P0;
    int   cnt = g_ecnt[dir];
    float inv = 1.f / g_dirsum[dir];
    int   off = dir ? 0 : 128;   // flow_total = [t2d | d2t]

    int nG = (cnt + 3) >> 2;
    int gu = blockIdx.x * 4 + unit;
    int stride = gridDim.x * 4;

    for (int g = gu; g < nG; g += stride) {
        int base = g * 4;
        int es[4], rows[4], cols[4];
        float attn[4];
        bool valid[4];
        #pragma unroll
        for (int s = 0; s < 4; s++) {
            int li = base + s;
            valid[s] = li < cnt;
            es[s] = elist[valid[s] ? li : 0];
            rows[s] = ei[es[s]];
            cols[s] = ei[N_EDGES + es[s]];
            attn[s] = valid[s] ? g_expv[es[s]] * inv : 0.f;
        }
        // load edge_attr transposed: eas[i*4+s]
        #pragma unroll
        for (int pass = 0; pass < 2; pass++) {
            int idx = t + pass * 128;
            int s = idx >> 6, i = idx & 63;
            eas[i * 4 + s] = eattr[(size_t)es[s] * EATTR + i];
        }
        barSync(barid);

        // GEMM1: edge_attr @ wbot  (outputs j=t and j=t+128, 4 edges)
        float a00 = 0, a01 = 0, a10 = 0, a11 = 0, a20 = 0, a21 = 0, a30 = 0, a31 = 0;
        #pragma unroll 8
        for (int i = 0; i < 64; i++) {
            float4 av = *reinterpret_cast<float4*>(&eas[i * 4]);
            float wlo = wbot[i * H + t];
            float whi = wbot[i * H + t + 128];
            a00 += av.x * wlo; a01 += av.x * whi;
            a10 += av.y * wlo; a11 += av.y * whi;
            a20 += av.z * wlo; a21 += av.z * whi;
            a30 += av.w * wlo; a31 += av.w * whi;
        }
        float b1lo = b1s[t], b1hi = b1s[t + 128];
        float h0[4], h1v[4];
        h0[0]  = attn[0] * (P[(size_t)cols[0] * H + t]       + a00) + b1lo;
        h1v[0] = attn[0] * (P[(size_t)cols[0] * H + t + 128] + a01) + b1hi;
        h0[1]  = attn[1] * (P[(size_t)cols[1] * H + t]       + a10) + b1lo;
        h1v[1] = attn[1] * (P[(size_t)cols[1] * H + t + 128] + a11) + b1hi;
        h0[2]  = attn[2] * (P[(size_t)cols[2] * H + t]       + a20) + b1lo;
        h1v[2] = attn[2] * (P[(size_t)cols[2] * H + t + 128] + a21) + b1hi;
        h0[3]  = attn[3] * (P[(size_t)cols[3] * H + t]       + a30) + b1lo;
        h1v[3] = attn[3] * (P[(size_t)cols[3] * H + t + 128] + a31) + b1hi;

        // LN over 256 (two-pass), then ReLU, store h1 transposed
        float sums[4];
        #pragma unroll
        for (int s = 0; s < 4; s++) sums[s] = h0[s] + h1v[s];
        ureduce<4>(sums, red, wu, lane, barid);
        float d0[4], d1[4], sq[4];
        #pragma unroll
        for (int s = 0; s < 4; s++) {
            float m = sums[s] * (1.f / 256.f);
            d0[s] = h0[s] - m;
            d1[s] = h1v[s] - m;
            sq[s] = d0[s] * d0[s] + d1[s] * d1[s];
        }
        ureduce<4>(sq, red, wu, lane, barid);
        float g1lo = g1s[t], g1hi = g1s[t + 128];
        float be1lo = be1s[t], be1hi = be1s[t + 128];
        #pragma unroll
        for (int s = 0; s < 4; s++) {
            float rstd = rsqrtf(sq[s] * (1.f / 256.f) + LN_EPS);
            float vlo = fmaxf(d0[s] * rstd * g1lo + be1lo, 0.f);
            float vhi = fmaxf(d1[s] * rstd * g1hi + be1hi, 0.f);
            h1s[t * 4 + s] = vlo;
            h1s[(t + 128) * 4 + s] = vhi;
        }
        barSync(barid);

        // GEMM2: h1 @ w2 -> 128 outputs, 4 edges
        float o0 = 0, o1 = 0, o2 = 0, o3 = 0;
        #pragma unroll 8
        for (int j = 0; j < H; j++) {
            float4 hv = *reinterpret_cast<float4*>(&h1s[j * 4]);
            float wv = w2s[j * 128 + t];
            o0 += hv.x * wv; o1 += hv.y * wv; o2 += hv.z * wv; o3 += hv.w * wv;
        }
        float bb = b2s[t];
        float oo[4] = { o0 + bb, o1 + bb, o2 + bb, o3 + bb };
        float s2[4] = { oo[0], oo[1], oo[2], oo[3] };
        ureduce<4>(s2, red, wu, lane, barid);
        float dd[4], qq[4];
        #pragma unroll
        for (int s = 0; s < 4; s++) {
            float m = s2[s] * (1.f / 128.f);
            dd[s] = oo[s] - m;
            qq[s] = dd[s] * dd[s];
        }
        ureduce<4>(qq, red, wu, lane, barid);
        float g2v = g2s[t], be2v = be2s[t];
        #pragma unroll
        for (int s = 0; s < 4; s++) {
            float rstd = rsqrtf(qq[s] * (1.f / 128.f) + LN_EPS);
            float v = fmaxf(dd[s] * rstd * g2v + be2v, 0.f);
            if (valid[s]) atomicAdd(&g_flow[(size_t)rows[s] * 256 + off + t], v);
        }
    }
}

// ---------------- node finalize ----------------
// SMEM float layout:
//   [0)      node_w 256*128 = 32768
//   [32768)  self_w 128*128 = 16384
//   [49152)  nb 128, ng 128, nbe 128, sb 128, sg 128, sbe 128
//   [49920)  4 units * 1568: flows_t 1024 | xns_t 512 | red 32
#define FINAL_SMEM_FLOATS (49920 + 4 * 1568)

__global__ void __launch_bounds__(512, 1) k_final(
    const float* __restrict__ x,
    const float* __restrict__ node_w, const float* __restrict__ node_b,
    const float* __restrict__ node_g, const float* __restrict__ node_be,
    const float* __restrict__ self_w, const float* __restrict__ self_b,
    const float* __restrict__ self_g, const float* __restrict__ self_be,
    float* __restrict__ out)
{
    extern __shared__ float sm[];
    float* nw = sm;
    float* sw = sm + 32768;
    float* nbv  = sm + 49152;
    float* ngv  = sm + 49280;
    float* nbev = sm + 49408;
    float* sbv  = sm + 49536;
    float* sgv  = sm + 49664;
    float* sbev = sm + 49792;
    for (int idx = threadIdx.x; idx < 32768; idx += 512) nw[idx] = node_w[idx];
    for (int idx = threadIdx.x; idx < 16384; idx += 512) sw[idx] = self_w[idx];
    if (threadIdx.x < 128) {
        int i = threadIdx.x;
        nbv[i] = node_b[i]; ngv[i] = node_g[i]; nbev[i] = node_be[i];
        sbv[i] = self_b[i]; sgv[i] = self_g[i]; sbev[i] = self_be[i];
    }
    __syncthreads();

    int unit = threadIdx.x >> 7;
    int t    = threadIdx.x & 127;
    int wu   = t >> 5;
    int lane = threadIdx.x & 31;
    int barid = unit + 1;
    float* U     = sm + 49920 + unit * 1568;
    float* flows = U;
    float* xns   = U + 1024;
    float* red   = U + 1536;

    int nG = (N_NODES + 3) >> 2;
    int gu = blockIdx.x * 4 + unit;
    int stride = gridDim.x * 4;

    for (int g = gu; g < nG; g += stride) {
        int base = g * 4;
        int nodes[4];
        bool valid[4];
        #pragma unroll
        for (int s = 0; s < 4; s++) {
            int n = base + s;
            valid[s] = n < N_NODES;
            nodes[s] = valid[s] ? n : 0;
        }
        #pragma unroll
        for (int pass = 0; pass < 8; pass++) {
            int idx = t + pass * 128;      // 0..1023
            int s = idx >> 8, j = idx & 255;
            flows[j * 4 + s] = g_flow[(size_t)nodes[s] * 256 + j];
        }
        #pragma unroll
        for (int pass = 0; pass < 4; pass++) {
            int idx = t + pass * 128;      // 0..511
            int s = idx >> 7, i = idx & 127;
            xns[i * 4 + s] = x[(size_t)nodes[s] * XW + i];
        }
        barSync(barid);

        float u0 = 0, u1 = 0, u2 = 0, u3 = 0;
        #pragma unroll 8
        for (int j = 0; j < 256; j++) {
            float4 fv = *reinterpret_cast<float4*>(&flows[j * 4]);
            float wv = nw[j * 128 + t];
            u0 += fv.x * wv; u1 += fv.y * wv; u2 += fv.z * wv; u3 += fv.w * wv;
        }
        float v0 = 0, v1 = 0, v2 = 0, v3 = 0;
        #pragma unroll 8
        for (int i = 0; i < 128; i++) {
            float4 xv = *reinterpret_cast<float4*>(&xns[i * 4]);
            float wv = sw[i * 128 + t];
            v0 += xv.x * wv; v1 += xv.y * wv; v2 += xv.z * wv; v3 += xv.w * wv;
        }
        float nb_ = nbv[t], sb_ = sbv[t];
        float uu[4] = { u0 + nb_, u1 + nb_, u2 + nb_, u3 + nb_ };
        float vv[4] = { v0 + sb_, v1 + sb_, v2 + sb_, v3 + sb_ };

        float sums[8] = { uu[0], uu[1], uu[2], uu[3], vv[0], vv[1], vv[2], vv[3] };
        ureduce<8>(sums, red, wu, lane, barid);
        float du[4], dv[4], sq[8];
        #pragma unroll
        for (int s = 0; s < 4; s++) {
            du[s] = uu[s] - sums[s] * (1.f / 128.f);
            dv[s] = vv[s] - sums[4 + s] * (1.f / 128.f);
            sq[s] = du[s] * du[s];
            sq[4 + s] = dv[s] * dv[s];
        }
        ureduce<8>(sq, red, wu, lane, barid);
        float ng_ = ngv[t], nbe_ = nbev[t], sg_ = sgv[t], sbe_ = sbev[t];
        #pragma unroll
        for (int s = 0; s < 4; s++) {
            float r1 = fmaxf(du[s] * rsqrtf(sq[s] * (1.f / 128.f) + LN_EPS) * ng_ + nbe_, 0.f);
            float r2 = fmaxf(dv[s] * rsqrtf(sq[4 + s] * (1.f / 128.f) + LN_EPS) * sg_ + sbe_, 0.f);
            if (valid[s]) out[(size_t)nodes[s] * XW + t] = r1 + r2;
        }
        if (t < 32) {
            #pragma unroll
            for (int s = 0; s < 4; s++) {
                if (valid[s])
                    out[(size_t)nodes[s] * XW + 128 + t] = x[(size_t)nodes[s] * XW + 128 + t];
            }
        }
    }
}

// ---------------- host ----------------
extern "C" void kernel_launch(void* const* d_in, const int* in_sizes, int n_in,
                              void* d_out, int out_size) {
    const float* x      = (const float*)d_in[0];
    const int*   ei     = (const int*)d_in[1];
    const float* eattr  = (const float*)d_in[2];
    const float* w_att  = (const float*)d_in[3];
    const float* b_att  = (const float*)d_in[4];
    const float* d2t_w1 = (const float*)d_in[5];
    const float* d2t_b1 = (const float*)d_in[6];
    const float* d2t_g1 = (const float*)d_in[7];
    const float* d2t_be1= (const float*)d_in[8];
    const float* d2t_w2 = (const float*)d_in[9];
    const float* d2t_b2 = (const float*)d_in[10];
    const float* d2t_g2 = (const float*)d_in[11];
    const float* d2t_be2= (const float*)d_in[12];
    const float* t2d_w1 = (const float*)d_in[13];
    const float* t2d_b1 = (const float*)d_in[14];
    const float* t2d_g1 = (const float*)d_in[15];
    const float* t2d_be1= (const float*)d_in[16];
    const float* t2d_w2 = (const float*)d_in[17];
    const float* t2d_b2 = (const float*)d_in[18];
    const float* t2d_g2 = (const float*)d_in[19];
    const float* t2d_be2= (const float*)d_in[20];
    const float* node_w = (const float*)d_in[21];
    const float* node_b = (const float*)d_in[22];
    const float* node_g = (const float*)d_in[23];
    const float* node_be= (const float*)d_in[24];
    const float* self_w = (const float*)d_in[25];
    const float* self_b = (const float*)d_in[26];
    const float* self_g = (const float*)d_in[27];
    const float* self_be= (const float*)d_in[28];
    float* out = (float*)d_out;

    const int EDGE_SMEM_BYTES  = EDGE_SMEM_FLOATS * 4;
    const int FINAL_SMEM_BYTES = FINAL_SMEM_FLOATS * 4;
    cudaFuncSetAttribute(k_edge,  cudaFuncAttributeMaxDynamicSharedMemorySize, EDGE_SMEM_BYTES);
    cudaFuncSetAttribute(k_final, cudaFuncAttributeMaxDynamicSharedMemorySize, FINAL_SMEM_BYTES);

    int initThreads = (int)((size_t)N_NODES * 256 / 4);
    k_init<<<(initThreads + 255) / 256, 256>>>();
    k_att_pre<<<(N_NODES + 7) / 8, 256>>>(x, w_att);
    k_node_pre<<<(N_NODES + 15) / 16, 256>>>(x, d2t_w1, t2d_w1);
    k_logit_max<<<(N_EDGES + 255) / 256, 256>>>(ei, b_att);
    k_sumexp<<<(N_EDGES + 255) / 256, 256>>>(ei);
    k_edge<<<148, 512, EDGE_SMEM_BYTES>>>(0, ei, eattr, d2t_w1,
        d2t_b1, d2t_g1, d2t_be1, d2t_w2, d2t_b2, d2t_g2, d2t_be2);
    k_edge<<<148, 512, EDGE_SMEM_BYTES>>>(1, ei, eattr, t2d_w1,
        t2d_b1, t2d_g1, t2d_be1, t2d_w2, t2d_b2, t2d_g2, t2d_be2);
    k_final<<<148, 512, FINAL_SMEM_BYTES>>>(x,
        node_w, node_b, node_g, node_be,
        self_w, self_b, self_g, self_be, out);
}

// round 2
// speedup vs baseline: 1.0367x; 1.0367x over previous
#include <cuda_runtime.h>
#include <math.h>
#include <stdint.h>

#define N_NODES 50000
#define N_EDGES 400000
#define D 128
#define H 256
#define EATTR 64
#define XW 160      /* D + SPLIT */
#define LN_EPS 1e-5f
#define SLOPE 0.01f
#define EPB 8       /* edges per 128-thread unit */

// ---------------- device scratch (no allocs allowed) ----------------
__device__ float g_P0[(size_t)N_NODES * H];   // xn @ d2t_w1_top
__device__ float g_P1[(size_t)N_NODES * H];   // xn @ t2d_w1_top
__device__ float g_acol[N_NODES];
__device__ float g_arow[N_NODES];
__device__ float g_expv[N_EDGES];             // exp(logit) (unshifted; logits ~N(0,1))
__device__ int   g_elist0[N_EDGES];
__device__ int   g_elist1[N_EDGES];
__device__ float g_flow[(size_t)N_NODES * 256];
__device__ float g_dirsum[2];
__device__ int   g_ecnt[2];

// ---------------- helpers ----------------
__device__ __forceinline__ void barSync(int id) {
    asm volatile("bar.sync %0, %1;" :: "r"(id), "r"(128) : "memory");
}

// reduce NV independent values across a 128-thread unit (4 warps)
template<int NV>
__device__ __forceinline__ void ureduce(float* v, float* red, int wu, int lane, int barid) {
    #pragma unroll
    for (int o = 16; o; o >>= 1) {
        #pragma unroll
        for (int k = 0; k < NV; k++) v[k] += __shfl_xor_sync(0xffffffffu, v[k], o);
    }
    if (lane == 0) {
        #pragma unroll
        for (int k = 0; k < NV; k++) red[wu * NV + k] = v[k];
    }
    barSync(barid);
    #pragma unroll
    for (int k = 0; k < NV; k++)
        v[k] = red[k] + red[NV + k] + red[2 * NV + k] + red[3 * NV + k];
    barSync(barid);
}

// ---------------- init + attention dots (merged) ----------------
__global__ void k_init_att(const float* __restrict__ x, const float* __restrict__ w_att) {
    size_t i = (size_t)blockIdx.x * blockDim.x + threadIdx.x;
    size_t n4 = (size_t)N_NODES * 256 / 4;
    if (i < n4) reinterpret_cast<float4*>(g_flow)[i] = make_float4(0.f, 0.f, 0.f, 0.f);
    if (i == 0) {
        g_dirsum[0] = 0.f; g_dirsum[1] = 0.f;
        g_ecnt[0] = 0; g_ecnt[1] = 0;
    }
    int gw = (int)(i >> 5);
    int lane = threadIdx.x & 31;
    if (gw < N_NODES) {
        const float* xr = x + (size_t)gw * XW;
        float s0 = 0.f, s1 = 0.f;
        #pragma unroll
        for (int k = lane; k < 128; k += 32) {
            float v = xr[k];
            s0 += v * w_att[k];
            s1 += v * w_att[128 + k];
        }
        #pragma unroll
        for (int o = 16; o; o >>= 1) {
            s0 += __shfl_xor_sync(0xffffffffu, s0, o);
            s1 += __shfl_xor_sync(0xffffffffu, s1, o);
        }
        if (lane == 0) { g_acol[gw] = s0; g_arow[gw] = s1; }
    }
}

// per-node P = xn @ W1_top for both directions (NB=16 nodes/block)
__global__ void k_node_pre(const float* __restrict__ x,
                           const float* __restrict__ w0,   // d2t_w1 (192x256)
                           const float* __restrict__ w1) { // t2d_w1
    __shared__ float xs[16 * 128];
    int nb = blockIdx.x * 16;
    for (int idx = threadIdx.x; idx < 16 * 128; idx += 256) {
        int nn = idx >> 7, i = idx & 127;
        int node = nb + nn;
        xs[idx] = (node < N_NODES) ? x[(size_t)node * XW + i] : 0.f;
    }
    __syncthreads();
    int j = threadIdx.x; // 0..255
    for (int d = 0; d < 2; d++) {
        const float* W = d ? w1 : w0;   // top 128 rows
        float* P = d ? g_P1 : g_P0;
        float acc[16];
        #pragma unroll
        for (int n = 0; n < 16; n++) acc[n] = 0.f;
        for (int i = 0; i < 128; i += 4) {
            float wv0 = __ldg(&W[(size_t)(i + 0) * H + j]);
            float wv1 = __ldg(&W[(size_t)(i + 1) * H + j]);
            float wv2 = __ldg(&W[(size_t)(i + 2) * H + j]);
            float wv3 = __ldg(&W[(size_t)(i + 3) * H + j]);
            #pragma unroll
            for (int n = 0; n < 16; n++) {
                float4 xv = *reinterpret_cast<float4*>(&xs[n * 128 + i]);
                acc[n] += xv.x * wv0 + xv.y * wv1 + xv.z * wv2 + xv.w * wv3;
            }
        }
        #pragma unroll
        for (int n = 0; n < 16; n++) {
            int node = nb + n;
            if (node < N_NODES) P[(size_t)node * H + j] = acc[n];
        }
    }
}

// exp(logit) + per-direction sum + compacted edge lists (no max pass: logits ~ N(0,1))
__global__ void k_sumexp(const int* __restrict__ ei, const float* __restrict__ b_att) {
    __shared__ int c0, c1, base0, base1;
    __shared__ float rs0[8], rs1[8];
    if (threadIdx.x == 0) { c0 = 0; c1 = 0; }
    __syncthreads();
    int e = blockIdx.x * blockDim.x + threadIdx.x;
    int dir = -1, pos = 0;
    float ex = 0.f;
    if (e < N_EDGES) {
        int r = ei[e], c = ei[N_EDGES + e];
        if (r < c) dir = 0; else if (r > c) dir = 1;
        if (dir >= 0) {
            float z = g_acol[c] + g_arow[r] + b_att[0];
            float lg = z > 0.f ? z : SLOPE * z;
            ex = expf(lg);
            pos = atomicAdd(dir ? &c1 : &c0, 1);
        }
        g_expv[e] = ex;
    }
    float v0 = (dir == 0) ? ex : 0.f;
    float v1 = (dir == 1) ? ex : 0.f;
    #pragma unroll
    for (int o = 16; o; o >>= 1) {
        v0 += __shfl_xor_sync(0xffffffffu, v0, o);
        v1 += __shfl_xor_sync(0xffffffffu, v1, o);
    }
    int w = threadIdx.x >> 5, l = threadIdx.x & 31;
    if (l == 0) { rs0[w] = v0; rs1[w] = v1; }
    __syncthreads();
    if (threadIdx.x == 0) {
        float t0 = 0.f, t1 = 0.f;
        for (int k = 0; k < 8; k++) { t0 += rs0[k]; t1 += rs1[k]; }
        if (t0 != 0.f) atomicAdd(&g_dirsum[0], t0);
        if (t1 != 0.f) atomicAdd(&g_dirsum[1], t1);
        base0 = c0 ? atomicAdd(&g_ecnt[0], c0) : 0;
        base1 = c1 ? atomicAdd(&g_ecnt[1], c1) : 0;
    }
    __syncthreads();
    if (dir == 0) g_elist0[base0 + pos] = e;
    else if (dir == 1) g_elist1[base1 + pos] = e;
}

// ---------------- fused edge MLP (8 edges per 128-thread unit, 3 units/CTA) ----------------
// SMEM float layout:
//   [0)       wbot 64*256 = 16384
//   [16384)   w2   256*128 = 32768
//   [49152)   b1 256, g1 256, be1 256
//   [49920)   b2 128, g2 128, be2 128
//   [50304)   3 units * 2144:
//               h1s 8*256 = 2048 (eas 8*64=512 aliases the front)
//               red 64
//               meta 32: e[8], row[8], col[8], attn[8]
#define UNIT_FLOATS 2144
#define EDGE_SMEM_FLOATS (50304 + 3 * UNIT_FLOATS)

__global__ void __launch_bounds__(384, 1) k_edge(
    int dir,
    const int* __restrict__ ei, const float* __restrict__ eattr,
    const float* __restrict__ w1full,
    const float* __restrict__ b1, const float* __restrict__ g1, const float* __restrict__ be1,
    const float* __restrict__ w2, const float* __restrict__ b2,
    const float* __restrict__ g2, const float* __restrict__ be2)
{
    extern __shared__ float sm[];
    float* wbot = sm;
    float* w2s  = sm + 16384;
    float* b1s  = sm + 49152;
    float* g1s  = sm + 49408;
    float* be1s = sm + 49664;
    float* b2s  = sm + 49920;
    float* g2s  = sm + 50048;
    float* be2s = sm + 50176;

    const float* wbg = w1full + 128 * H;
    for (int idx = threadIdx.x; idx < 16384; idx += 384) wbot[idx] = wbg[idx];
    for (int idx = threadIdx.x; idx < 32768; idx += 384) w2s[idx] = w2[idx];
    if (threadIdx.x < 256) {
        b1s[threadIdx.x]  = b1[threadIdx.x];
        g1s[threadIdx.x]  = g1[threadIdx.x];
        be1s[threadIdx.x] = be1[threadIdx.x];
    }
    if (threadIdx.x < 128) {
        b2s[threadIdx.x]  = b2[threadIdx.x];
        g2s[threadIdx.x]  = g2[threadIdx.x];
        be2s[threadIdx.x] = be2[threadIdx.x];
    }
    __syncthreads();

    int unit = threadIdx.x >> 7;   // 0..2
    int t    = threadIdx.x & 127;
    int wu   = t >> 5;
    int lane = threadIdx.x & 31;
    int barid = unit + 1;
    float* U    = sm + 50304 + unit * UNIT_FLOATS;
    float* h1s  = U;          // 2048; eas aliases first 512
    float* eas  = U;
    float* red  = U + 2048;   // 64
    float* meta = U + 2112;   // 32

    const int*   elist = dir ? g_elist1 : g_elist0;
    const float* P     = dir ? g_P1 : g_P0;
    int   cnt = g_ecnt[dir];
    float inv = 1.f / g_dirsum[dir];
    int   off = dir ? 0 : 128;   // flow_total = [t2d | d2t]

    int nG = (cnt + EPB - 1) / EPB;
    int gu = blockIdx.x * 3 + unit;
    int stride = gridDim.x * 3;

    int s8 = t & 7;        // edge slot this thread loads
    int f4 = t >> 3;       // float4 index within edge_attr row (0..15)

    for (int g = gu; g < nG; g += stride) {
        int base = g * EPB;

        // --- gather edge_attr (row-major per edge) + metadata ---
        {
            int li = base + s8;
            int ee = elist[li < cnt ? li : 0];
            float4 ev = *reinterpret_cast<const float4*>(&eattr[(size_t)ee * EATTR + f4 * 4]);
            *reinterpret_cast<float4*>(&eas[s8 * 64 + f4 * 4]) = ev;
            if (t < EPB) {
                int r = ei[ee], c = ei[N_EDGES + ee];
                meta[t]      = (li < cnt) ? g_expv[ee] * inv : 0.f;   // attn
                meta[8 + t]  = __int_as_float(r);
                meta[16 + t] = __int_as_float(c);
            }
        }
        barSync(barid);

        float attn[EPB];
        int rows[EPB], cols[EPB];
        #pragma unroll
        for (int s = 0; s < EPB; s++) {
            attn[s] = meta[s];
            rows[s] = __float_as_int(meta[8 + s]);
            cols[s] = __float_as_int(meta[16 + s]);
        }

        // prefetch P rows (features 2t, 2t+1), coalesced float2 gathers
        float2 pv[EPB];
        #pragma unroll
        for (int s = 0; s < EPB; s++)
            pv[s] = *reinterpret_cast<const float2*>(&P[(size_t)cols[s] * H + 2 * t]);

        // --- GEMM1: edge_attr @ wbot, outputs features 2t, 2t+1 for 8 edges ---
        float a0[EPB], a1[EPB];
        #pragma unroll
        for (int s = 0; s < EPB; s++) { a0[s] = 0.f; a1[s] = 0.f; }
        #pragma unroll 4
        for (int i = 0; i < 64; i += 4) {
            float2 w0 = *reinterpret_cast<float2*>(&wbot[(i + 0) * H + 2 * t]);
            float2 w1v = *reinterpret_cast<float2*>(&wbot[(i + 1) * H + 2 * t]);
            float2 w2v = *reinterpret_cast<float2*>(&wbot[(i + 2) * H + 2 * t]);
            float2 w3v = *reinterpret_cast<float2*>(&wbot[(i + 3) * H + 2 * t]);
            #pragma unroll
            for (int s = 0; s < EPB; s++) {
                float4 e4 = *reinterpret_cast<float4*>(&eas[s * 64 + i]);
                a0[s] += e4.x * w0.x + e4.y * w1v.x + e4.z * w2v.x + e4.w * w3v.x;
                a1[s] += e4.x * w0.y + e4.y * w1v.y + e4.z * w2v.y + e4.w * w3v.y;
            }
        }

        float2 b1v  = *reinterpret_cast<float2*>(&b1s[2 * t]);
        float h0[EPB], h1[EPB];
        #pragma unroll
        for (int s = 0; s < EPB; s++) {
            h0[s] = attn[s] * (pv[s].x + a0[s]) + b1v.x;
            h1[s] = attn[s] * (pv[s].y + a1[s]) + b1v.y;
        }

        // --- LN1 (fused mean/var) + ReLU, store h1s row-major per edge ---
        float v[16];
        #pragma unroll
        for (int s = 0; s < EPB; s++) {
            v[2 * s]     = h0[s] + h1[s];
            v[2 * s + 1] = h0[s] * h0[s] + h1[s] * h1[s];
        }
        ureduce<16>(v, red, wu, lane, barid);
        float2 g1v  = *reinterpret_cast<float2*>(&g1s[2 * t]);
        float2 be1v = *reinterpret_cast<float2*>(&be1s[2 * t]);
        #pragma unroll
        for (int s = 0; s < EPB; s++) {
            float m = v[2 * s] * (1.f / 256.f);
            float var = fmaxf(v[2 * s + 1] * (1.f / 256.f) - m * m, 0.f);
            float rstd = rsqrtf(var + LN_EPS);
            float vlo = fmaxf((h0[s] - m) * rstd * g1v.x + be1v.x, 0.f);
            float vhi = fmaxf((h1[s] - m) * rstd * g1v.y + be1v.y, 0.f);
            *reinterpret_cast<float2*>(&h1s[s * H + 2 * t]) = make_float2(vlo, vhi);
        }
        barSync(barid);

        // --- GEMM2: h1 @ w2 -> output feature t for 8 edges ---
        float o[EPB];
        #pragma unroll
        for (int s = 0; s < EPB; s++) o[s] = 0.f;
        #pragma unroll 8
        for (int f = 0; f < H; f += 4) {
            float wA = w2s[(f + 0) * 128 + t];
            float wB = w2s[(f + 1) * 128 + t];
            float wC = w2s[(f + 2) * 128 + t];
            float wD = w2s[(f + 3) * 128 + t];
            #pragma unroll
            for (int s = 0; s < EPB; s++) {
                float4 hh = *reinterpret_cast<float4*>(&h1s[s * H + f]);
                o[s] += hh.x * wA + hh.y * wB + hh.z * wC + hh.w * wD;
            }
        }
        float bb = b2s[t];
        #pragma unroll
        for (int s = 0; s < EPB; s++) o[s] += bb;

        // --- LN2 (fused) + ReLU + scatter-add ---
        float v2[16];
        #pragma unroll
        for (int s = 0; s < EPB; s++) {
            v2[2 * s]     = o[s];
            v2[2 * s + 1] = o[s] * o[s];
        }
        ureduce<16>(v2, red, wu, lane, barid);
        float g2v = g2s[t], be2v = be2s[t];
        #pragma unroll
        for (int s = 0; s < EPB; s++) {
            float m = v2[2 * s] * (1.f / 128.f);
            float var = fmaxf(v2[2 * s + 1] * (1.f / 128.f) - m * m, 0.f);
            float rstd = rsqrtf(var + LN_EPS);
            float val = fmaxf((o[s] - m) * rstd * g2v + be2v, 0.f);
            if (base + s < cnt)
                atomicAdd(&g_flow[(size_t)rows[s] * 256 + off + t], val);
        }
    }
}

// ---------------- node finalize ----------------
// SMEM float layout:
//   [0)      node_w 256*128 = 32768
//   [32768)  self_w 128*128 = 16384
//   [49152)  nb 128, ng 128, nbe 128, sb 128, sg 128, sbe 128
//   [49920)  4 units * 1568: flows_t 1024 | xns_t 512 | red 32
#define FINAL_SMEM_FLOATS (49920 + 4 * 1568)

__global__ void __launch_bounds__(512, 1) k_final(
    const float* __restrict__ x,
    const float* __restrict__ node_w, const float* __restrict__ node_b,
    const float* __restrict__ node_g, const float* __restrict__ node_be,
    const float* __restrict__ self_w, const float* __restrict__ self_b,
    const float* __restrict__ self_g, const float* __restrict__ self_be,
    float* __restrict__ out)
{
    extern __shared__ float sm[];
    float* nw = sm;
    float* sw = sm + 32768;
    float* nbv  = sm + 49152;
    float* ngv  = sm + 49280;
    float* nbev = sm + 49408;
    float* sbv  = sm + 49536;
    float* sgv  = sm + 49664;
    float* sbev = sm + 49792;
    for (int idx = threadIdx.x; idx < 32768; idx += 512) nw[idx] = node_w[idx];
    for (int idx = threadIdx.x; idx < 16384; idx += 512) sw[idx] = self_w[idx];
    if (threadIdx.x < 128) {
        int i = threadIdx.x;
        nbv[i] = node_b[i]; ngv[i] = node_g[i]; nbev[i] = node_be[i];
        sbv[i] = self_b[i]; sgv[i] = self_g[i]; sbev[i] = self_be[i];
    }
    __syncthreads();

    int unit = threadIdx.x >> 7;
    int t    = threadIdx.x & 127;
    int wu   = t >> 5;
    int lane = threadIdx.x & 31;
    int barid = unit + 1;
    float* U     = sm + 49920 + unit * 1568;
    float* flows = U;
    float* xns   = U + 1024;
    float* red   = U + 1536;

    int nG = (N_NODES + 3) >> 2;
    int gu = blockIdx.x * 4 + unit;
    int stride = gridDim.x * 4;

    for (int g = gu; g < nG; g += stride) {
        int base = g * 4;
        int nodes[4];
        bool valid[4];
        #pragma unroll
        for (int s = 0; s < 4; s++) {
            int n = base + s;
            valid[s] = n < N_NODES;
            nodes[s] = valid[s] ? n : 0;
        }
        #pragma unroll
        for (int pass = 0; pass < 8; pass++) {
            int idx = t + pass * 128;      // 0..1023
            int s = idx >> 8, j = idx & 255;
            flows[j * 4 + s] = g_flow[(size_t)nodes[s] * 256 + j];
        }
        #pragma unroll
        for (int pass = 0; pass < 4; pass++) {
            int idx = t + pass * 128;      // 0..511
            int s = idx >> 7, i = idx & 127;
            xns[i * 4 + s] = x[(size_t)nodes[s] * XW + i];
        }
        barSync(barid);

        float u0 = 0, u1 = 0, u2 = 0, u3 = 0;
        #pragma unroll 8
        for (int j = 0; j < 256; j++) {
            float4 fv = *reinterpret_cast<float4*>(&flows[j * 4]);
            float wv = nw[j * 128 + t];
            u0 += fv.x * wv; u1 += fv.y * wv; u2 += fv.z * wv; u3 += fv.w * wv;
        }
        float v0 = 0, v1 = 0, v2 = 0, v3 = 0;
        #pragma unroll 8
        for (int i = 0; i < 128; i++) {
            float4 xv = *reinterpret_cast<float4*>(&xns[i * 4]);
            float wv = sw[i * 128 + t];
            v0 += xv.x * wv; v1 += xv.y * wv; v2 += xv.z * wv; v3 += xv.w * wv;
        }
        float nb_ = nbv[t], sb_ = sbv[t];
        float uu[4] = { u0 + nb_, u1 + nb_, u2 + nb_, u3 + nb_ };
        float vv[4] = { v0 + sb_, v1 + sb_, v2 + sb_, v3 + sb_ };

        float sums[8] = { uu[0], uu[1], uu[2], uu[3], vv[0], vv[1], vv[2], vv[3] };
        ureduce<8>(sums, red, wu, lane, barid);
        float du[4], dv[4], sq[8];
        #pragma unroll
        for (int s = 0; s < 4; s++) {
            du[s] = uu[s] - sums[s] * (1.f / 128.f);
            dv[s] = vv[s] - sums[4 + s] * (1.f / 128.f);
            sq[s] = du[s] * du[s];
            sq[4 + s] = dv[s] * dv[s];
        }
        ureduce<8>(sq, red, wu, lane, barid);
        float ng_ = ngv[t], nbe_ = nbev[t], sg_ = sgv[t], sbe_ = sbev[t];
        #pragma unroll
        for (int s = 0; s < 4; s++) {
            float r1 = fmaxf(du[s] * rsqrtf(sq[s] * (1.f / 128.f) + LN_EPS) * ng_ + nbe_, 0.f);
            float r2 = fmaxf(dv[s] * rsqrtf(sq[4 + s] * (1.f / 128.f) + LN_EPS) * sg_ + sbe_, 0.f);
            if (valid[s]) out[(size_t)nodes[s] * XW + t] = r1 + r2;
        }
        if (t < 32) {
            #pragma unroll
            for (int s = 0; s < 4; s++) {
                if (valid[s])
                    out[(size_t)nodes[s] * XW + 128 + t] = x[(size_t)nodes[s] * XW + 128 + t];
            }
        }
    }
}

// ---------------- host ----------------
extern "C" void kernel_launch(void* const* d_in, const int* in_sizes, int n_in,
                              void* d_out, int out_size) {
    const float* x      = (const float*)d_in[0];
    const int*   ei     = (const int*)d_in[1];
    const float* eattr  = (const float*)d_in[2];
    const float* w_att  = (const float*)d_in[3];
    const float* b_att  = (const float*)d_in[4];
    const float* d2t_w1 = (const float*)d_in[5];
    const float* d2t_b1 = (const float*)d_in[6];
    const float* d2t_g1 = (const float*)d_in[7];
    const float* d2t_be1= (const float*)d_in[8];
    const float* d2t_w2 = (const float*)d_in[9];
    const float* d2t_b2 = (const float*)d_in[10];
    const float* d2t_g2 = (const float*)d_in[11];
    const float* d2t_be2= (const float*)d_in[12];
    const float* t2d_w1 = (const float*)d_in[13];
    const float* t2d_b1 = (const float*)d_in[14];
    const float* t2d_g1 = (const float*)d_in[15];
    const float* t2d_be1= (const float*)d_in[16];
    const float* t2d_w2 = (const float*)d_in[17];
    const float* t2d_b2 = (const float*)d_in[18];
    const float* t2d_g2 = (const float*)d_in[19];
    const float* t2d_be2= (const float*)d_in[20];
    const float* node_w = (const float*)d_in[21];
    const float* node_b = (const float*)d_in[22];
    const float* node_g = (const float*)d_in[23];
    const float* node_be= (const float*)d_in[24];
    const float* self_w = (const float*)d_in[25];
    const float* self_b = (const float*)d_in[26];
    const float* self_g = (const float*)d_in[27];
    const float* self_be= (const float*)d_in[28];
    float* out = (float*)d_out;

    const int EDGE_SMEM_BYTES  = EDGE_SMEM_FLOATS * 4;
    const int FINAL_SMEM_BYTES = FINAL_SMEM_FLOATS * 4;
    cudaFuncSetAttribute(k_edge,  cudaFuncAttributeMaxDynamicSharedMemorySize, EDGE_SMEM_BYTES);
    cudaFuncSetAttribute(k_final, cudaFuncAttributeMaxDynamicSharedMemorySize, FINAL_SMEM_BYTES);

    int initThreads = (int)((size_t)N_NODES * 256 / 4);
    k_init_att<<<(initThreads + 255) / 256, 256>>>(x, w_att);
    k_node_pre<<<(N_NODES + 15) / 16, 256>>>(x, d2t_w1, t2d_w1);
    k_sumexp<<<(N_EDGES + 255) / 256, 256>>>(ei, b_att);
    k_edge<<<148, 384, EDGE_SMEM_BYTES>>>(0, ei, eattr, d2t_w1,
        d2t_b1, d2t_g1, d2t_be1, d2t_w2, d2t_b2, d2t_g2, d2t_be2);
    k_edge<<<148, 384, EDGE_SMEM_BYTES>>>(1, ei, eattr, t2d_w1,
        t2d_b1, t2d_g1, t2d_be1, t2d_w2, t2d_b2, t2d_g2, t2d_be2);
    k_final<<<148, 512, FINAL_SMEM_BYTES>>>(x,
        node_w, node_b, node_g, node_be,
        self_w, self_b, self_g, self_be, out);
}

// round 3
// speedup vs baseline: 1.0385x; 1.0017x over previous
#include <cuda_runtime.h>
#include <math.h>
#include <stdint.h>

#define N_NODES 50000
#define N_EDGES 400000
#define D 128
#define H 256
#define EATTR 64
#define XW 160      /* D + SPLIT */
#define LN_EPS 1e-5f
#define SLOPE 0.01f
#define EPB 8       /* edges per 128-thread unit */

// ---------------- device scratch (no allocs allowed) ----------------
__device__ float g_P0[(size_t)N_NODES * H];   // xn @ d2t_w1_top
__device__ float g_P1[(size_t)N_NODES * H];   // xn @ t2d_w1_top
__device__ float g_acol[N_NODES];
__device__ float g_arow[N_NODES];
__device__ float g_expv[N_EDGES];             // exp(logit) (unshifted; logits ~N(0,1))
__device__ int   g_elist0[N_EDGES];
__device__ int   g_elist1[N_EDGES];
__device__ float g_flow[(size_t)N_NODES * 256];
__device__ float g_dirsum[2];
__device__ int   g_ecnt[2];

// ---------------- helpers ----------------
__device__ __forceinline__ void barSync(int id) {
    asm volatile("bar.sync %0, %1;" :: "r"(id), "r"(128) : "memory");
}

// reduce NV independent values across a 128-thread unit (4 warps)
template<int NV>
__device__ __forceinline__ void ureduce(float* v, float* red, int wu, int lane, int barid) {
    #pragma unroll
    for (int o = 16; o; o >>= 1) {
        #pragma unroll
        for (int k = 0; k < NV; k++) v[k] += __shfl_xor_sync(0xffffffffu, v[k], o);
    }
    if (lane == 0) {
        #pragma unroll
        for (int k = 0; k < NV; k++) red[wu * NV + k] = v[k];
    }
    barSync(barid);
    #pragma unroll
    for (int k = 0; k < NV; k++)
        v[k] = red[k] + red[NV + k] + red[2 * NV + k] + red[3 * NV + k];
    barSync(barid);
}

// ---------------- init + attention dots (merged) ----------------
__global__ void k_init_att(const float* __restrict__ x, const float* __restrict__ w_att) {
    size_t i = (size_t)blockIdx.x * blockDim.x + threadIdx.x;
    size_t n4 = (size_t)N_NODES * 256 / 4;
    if (i < n4) reinterpret_cast<float4*>(g_flow)[i] = make_float4(0.f, 0.f, 0.f, 0.f);
    if (i == 0) {
        g_dirsum[0] = 0.f; g_dirsum[1] = 0.f;
        g_ecnt[0] = 0; g_ecnt[1] = 0;
    }
    int gw = (int)(i >> 5);
    int lane = threadIdx.x & 31;
    if (gw < N_NODES) {
        const float* xr = x + (size_t)gw * XW;
        float s0 = 0.f, s1 = 0.f;
        #pragma unroll
        for (int k = lane; k < 128; k += 32) {
            float v = xr[k];
            s0 += v * w_att[k];
            s1 += v * w_att[128 + k];
        }
        #pragma unroll
        for (int o = 16; o; o >>= 1) {
            s0 += __shfl_xor_sync(0xffffffffu, s0, o);
            s1 += __shfl_xor_sync(0xffffffffu, s1, o);
        }
        if (lane == 0) { g_acol[gw] = s0; g_arow[gw] = s1; }
    }
}

// per-node P = xn @ W1_top for both directions (NB=16 nodes/block)
__global__ void k_node_pre(const float* __restrict__ x,
                           const float* __restrict__ w0,   // d2t_w1 (192x256)
                           const float* __restrict__ w1) { // t2d_w1
    __shared__ float xs[16 * 128];
    int nb = blockIdx.x * 16;
    for (int idx = threadIdx.x; idx < 16 * 128; idx += 256) {
        int nn = idx >> 7, i = idx & 127;
        int node = nb + nn;
        xs[idx] = (node < N_NODES) ? x[(size_t)node * XW + i] : 0.f;
    }
    __syncthreads();
    int j = threadIdx.x; // 0..255
    for (int d = 0; d < 2; d++) {
        const float* W = d ? w1 : w0;   // top 128 rows
        float* P = d ? g_P1 : g_P0;
        float acc[16];
        #pragma unroll
        for (int n = 0; n < 16; n++) acc[n] = 0.f;
        for (int i = 0; i < 128; i += 4) {
            float wv0 = __ldg(&W[(size_t)(i + 0) * H + j]);
            float wv1 = __ldg(&W[(size_t)(i + 1) * H + j]);
            float wv2 = __ldg(&W[(size_t)(i + 2) * H + j]);
            float wv3 = __ldg(&W[(size_t)(i + 3) * H + j]);
            #pragma unroll
            for (int n = 0; n < 16; n++) {
                float4 xv = *reinterpret_cast<float4*>(&xs[n * 128 + i]);
                acc[n] += xv.x * wv0 + xv.y * wv1 + xv.z * wv2 + xv.w * wv3;
            }
        }
        #pragma unroll
        for (int n = 0; n < 16; n++) {
            int node = nb + n;
            if (node < N_NODES) P[(size_t)node * H + j] = acc[n];
        }
    }
}

// exp(logit) + per-direction sum + compacted edge lists (no max pass: logits ~ N(0,1))
__global__ void k_sumexp(const int* __restrict__ ei, const float* __restrict__ b_att) {
    __shared__ int c0, c1, base0, base1;
    __shared__ float rs0[8], rs1[8];
    if (threadIdx.x == 0) { c0 = 0; c1 = 0; }
    __syncthreads();
    int e = blockIdx.x * blockDim.x + threadIdx.x;
    int dir = -1, pos = 0;
    float ex = 0.f;
    if (e < N_EDGES) {
        int r = ei[e], c = ei[N_EDGES + e];
        if (r < c) dir = 0; else if (r > c) dir = 1;
        if (dir >= 0) {
            float z = g_acol[c] + g_arow[r] + b_att[0];
            float lg = z > 0.f ? z : SLOPE * z;
            ex = expf(lg);
            pos = atomicAdd(dir ? &c1 : &c0, 1);
        }
        g_expv[e] = ex;
    }
    float v0 = (dir == 0) ? ex : 0.f;
    float v1 = (dir == 1) ? ex : 0.f;
    #pragma unroll
    for (int o = 16; o; o >>= 1) {
        v0 += __shfl_xor_sync(0xffffffffu, v0, o);
        v1 += __shfl_xor_sync(0xffffffffu, v1, o);
    }
    int w = threadIdx.x >> 5, l = threadIdx.x & 31;
    if (l == 0) { rs0[w] = v0; rs1[w] = v1; }
    __syncthreads();
    if (threadIdx.x == 0) {
        float t0 = 0.f, t1 = 0.f;
        for (int k = 0; k < 8; k++) { t0 += rs0[k]; t1 += rs1[k]; }
        if (t0 != 0.f) atomicAdd(&g_dirsum[0], t0);
        if (t1 != 0.f) atomicAdd(&g_dirsum[1], t1);
        base0 = c0 ? atomicAdd(&g_ecnt[0], c0) : 0;
        base1 = c1 ? atomicAdd(&g_ecnt[1], c1) : 0;
    }
    __syncthreads();
    if (dir == 0) g_elist0[base0 + pos] = e;
    else if (dir == 1) g_elist1[base1 + pos] = e;
}

// ---------------- fused edge MLP (8 edges per 128-thread unit, 3 units/CTA) ----------------
// SMEM float layout:
//   [0)       wbot 64*256 = 16384
//   [16384)   w2   256*128 = 32768
//   [49152)   b1 256, g1 256, be1 256
//   [49920)   b2 128, g2 128, be2 128
//   [50304)   3 units * 2144:
//               h1s 8*256 = 2048 (eas 8*64=512 aliases the front)
//               red 64
//               meta 32: e[8], row[8], col[8], attn[8]
#define UNIT_FLOATS 2144
#define EDGE_SMEM_FLOATS (50304 + 3 * UNIT_FLOATS)

__global__ void __launch_bounds__(384, 1) k_edge(
    int dir,
    const int* __restrict__ ei, const float* __restrict__ eattr,
    const float* __restrict__ w1full,
    const float* __restrict__ b1, const float* __restrict__ g1, const float* __restrict__ be1,
    const float* __restrict__ w2, const float* __restrict__ b2,
    const float* __restrict__ g2, const float* __restrict__ be2)
{
    extern __shared__ float sm[];
    float* wbot = sm;
    float* w2s  = sm + 16384;
    float* b1s  = sm + 49152;
    float* g1s  = sm + 49408;
    float* be1s = sm + 49664;
    float* b2s  = sm + 49920;
    float* g2s  = sm + 50048;
    float* be2s = sm + 50176;

    const float* wbg = w1full + 128 * H;
    for (int idx = threadIdx.x; idx < 16384; idx += 384) wbot[idx] = wbg[idx];
    for (int idx = threadIdx.x; idx < 32768; idx += 384) w2s[idx] = w2[idx];
    if (threadIdx.x < 256) {
        b1s[threadIdx.x]  = b1[threadIdx.x];
        g1s[threadIdx.x]  = g1[threadIdx.x];
        be1s[threadIdx.x] = be1[threadIdx.x];
    }
    if (threadIdx.x < 128) {
        b2s[threadIdx.x]  = b2[threadIdx.x];
        g2s[threadIdx.x]  = g2[threadIdx.x];
        be2s[threadIdx.x] = be2[threadIdx.x];
    }
    __syncthreads();

    int unit = threadIdx.x >> 7;   // 0..2
    int t    = threadIdx.x & 127;
    int wu   = t >> 5;
    int lane = threadIdx.x & 31;
    int barid = unit + 1;
    float* U    = sm + 50304 + unit * UNIT_FLOATS;
    float* h1s  = U;          // 2048; eas aliases first 512
    float* eas  = U;
    float* red  = U + 2048;   // 64
    float* meta = U + 2112;   // 32

    const int*   elist = dir ? g_elist1 : g_elist0;
    const float* P     = dir ? g_P1 : g_P0;
    int   cnt = g_ecnt[dir];
    float inv = 1.f / g_dirsum[dir];
    int   off = dir ? 0 : 128;   // flow_total = [t2d | d2t]

    int nG = (cnt + EPB - 1) / EPB;
    int gu = blockIdx.x * 3 + unit;
    int stride = gridDim.x * 3;

    int s8 = t & 7;        // edge slot this thread loads
    int f4 = t >> 3;       // float4 index within edge_attr row (0..15)

    for (int g = gu; g < nG; g += stride) {
        int base = g * EPB;

        // --- gather edge_attr (row-major per edge) + metadata ---
        {
            int li = base + s8;
            int ee = elist[li < cnt ? li : 0];
            float4 ev = *reinterpret_cast<const float4*>(&eattr[(size_t)ee * EATTR + f4 * 4]);
            *reinterpret_cast<float4*>(&eas[s8 * 64 + f4 * 4]) = ev;
            if (t < EPB) {
                int r = ei[ee], c = ei[N_EDGES + ee];
                meta[t]      = (li < cnt) ? g_expv[ee] * inv : 0.f;   // attn
                meta[8 + t]  = __int_as_float(r);
                meta[16 + t] = __int_as_float(c);
            }
        }
        barSync(barid);

        float attn[EPB];
        int rows[EPB], cols[EPB];
        #pragma unroll
        for (int s = 0; s < EPB; s++) {
            attn[s] = meta[s];
            rows[s] = __float_as_int(meta[8 + s]);
            cols[s] = __float_as_int(meta[16 + s]);
        }

        // prefetch P rows (features 2t, 2t+1), coalesced float2 gathers
        float2 pv[EPB];
        #pragma unroll
        for (int s = 0; s < EPB; s++)
            pv[s] = *reinterpret_cast<const float2*>(&P[(size_t)cols[s] * H + 2 * t]);

        // --- GEMM1: edge_attr @ wbot, outputs features 2t, 2t+1 for 8 edges ---
        float a0[EPB], a1[EPB];
        #pragma unroll
        for (int s = 0; s < EPB; s++) { a0[s] = 0.f; a1[s] = 0.f; }
        #pragma unroll 4
        for (int i = 0; i < 64; i += 4) {
            float2 w0 = *reinterpret_cast<float2*>(&wbot[(i + 0) * H + 2 * t]);
            float2 w1v = *reinterpret_cast<float2*>(&wbot[(i + 1) * H + 2 * t]);
            float2 w2v = *reinterpret_cast<float2*>(&wbot[(i + 2) * H + 2 * t]);
            float2 w3v = *reinterpret_cast<float2*>(&wbot[(i + 3) * H + 2 * t]);
            #pragma unroll
            for (int s = 0; s < EPB; s++) {
                float4 e4 = *reinterpret_cast<float4*>(&eas[s * 64 + i]);
                a0[s] += e4.x * w0.x + e4.y * w1v.x + e4.z * w2v.x + e4.w * w3v.x;
                a1[s] += e4.x * w0.y + e4.y * w1v.y + e4.z * w2v.y + e4.w * w3v.y;
            }
        }

        float2 b1v  = *reinterpret_cast<float2*>(&b1s[2 * t]);
        float h0[EPB], h1[EPB];
        #pragma unroll
        for (int s = 0; s < EPB; s++) {
            h0[s] = attn[s] * (pv[s].x + a0[s]) + b1v.x;
            h1[s] = attn[s] * (pv[s].y + a1[s]) + b1v.y;
        }

        // --- LN1 (fused mean/var) + ReLU, store h1s row-major per edge ---
        float v[16];
        #pragma unroll
        for (int s = 0; s < EPB; s++) {
            v[2 * s]     = h0[s] + h1[s];
            v[2 * s + 1] = h0[s] * h0[s] + h1[s] * h1[s];
        }
        ureduce<16>(v, red, wu, lane, barid);
        float2 g1v  = *reinterpret_cast<float2*>(&g1s[2 * t]);
        float2 be1v = *reinterpret_cast<float2*>(&be1s[2 * t]);
        #pragma unroll
        for (int s = 0; s < EPB; s++) {
            float m = v[2 * s] * (1.f / 256.f);
            float var = fmaxf(v[2 * s + 1] * (1.f / 256.f) - m * m, 0.f);
            float rstd = rsqrtf(var + LN_EPS);
            float vlo = fmaxf((h0[s] - m) * rstd * g1v.x + be1v.x, 0.f);
            float vhi = fmaxf((h1[s] - m) * rstd * g1v.y + be1v.y, 0.f);
            *reinterpret_cast<float2*>(&h1s[s * H + 2 * t]) = make_float2(vlo, vhi);
        }
        barSync(barid);

        // --- GEMM2: h1 @ w2 -> output feature t for 8 edges ---
        float o[EPB];
        #pragma unroll
        for (int s = 0; s < EPB; s++) o[s] = 0.f;
        #pragma unroll 8
        for (int f = 0; f < H; f += 4) {
            float wA = w2s[(f + 0) * 128 + t];
            float wB = w2s[(f + 1) * 128 + t];
            float wC = w2s[(f + 2) * 128 + t];
            float wD = w2s[(f + 3) * 128 + t];
            #pragma unroll
            for (int s = 0; s < EPB; s++) {
                float4 hh = *reinterpret_cast<float4*>(&h1s[s * H + f]);
                o[s] += hh.x * wA + hh.y * wB + hh.z * wC + hh.w * wD;
            }
        }
        float bb = b2s[t];
        #pragma unroll
        for (int s = 0; s < EPB; s++) o[s] += bb;

        // --- LN2 (fused) + ReLU + scatter-add ---
        float v2[16];
        #pragma unroll
        for (int s = 0; s < EPB; s++) {
            v2[2 * s]     = o[s];
            v2[2 * s + 1] = o[s] * o[s];
        }
        ureduce<16>(v2, red, wu, lane, barid);
        float g2v = g2s[t], be2v = be2s[t];
        #pragma unroll
        for (int s = 0; s < EPB; s++) {
            float m = v2[2 * s] * (1.f / 128.f);
            float var = fmaxf(v2[2 * s + 1] * (1.f / 128.f) - m * m, 0.f);
            float rstd = rsqrtf(var + LN_EPS);
            float val = fmaxf((o[s] - m) * rstd * g2v + be2v, 0.f);
            if (base + s < cnt)
                atomicAdd(&g_flow[(size_t)rows[s] * 256 + off + t], val);
        }
    }
}

// ---------------- node finalize ----------------
// SMEM float layout:
//   [0)      node_w 256*128 = 32768
//   [32768)  self_w 128*128 = 16384
//   [49152)  nb 128, ng 128, nbe 128, sb 128, sg 128, sbe 128
//   [49920)  4 units * 1568: flows_t 1024 | xns_t 512 | red 32
#define FINAL_SMEM_FLOATS (49920 + 4 * 1568)

__global__ void __launch_bounds__(512, 1) k_final(
    const float* __restrict__ x,
    const float* __restrict__ node_w, const float* __restrict__ node_b,
    const float* __restrict__ node_g, const float* __restrict__ node_be,
    const float* __restrict__ self_w, const float* __restrict__ self_b,
    const float* __restrict__ self_g, const float* __restrict__ self_be,
    float* __restrict__ out)
{
    extern __shared__ float sm[];
    float* nw = sm;
    float* sw = sm + 32768;
    float* nbv  = sm + 49152;
    float* ngv  = sm + 49280;
    float* nbev = sm + 49408;
    float* sbv  = sm + 49536;
    float* sgv  = sm + 49664;
    float* sbev = sm + 49792;
    for (int idx = threadIdx.x; idx < 32768; idx += 512) nw[idx] = node_w[idx];
    for (int idx = threadIdx.x; idx < 16384; idx += 512) sw[idx] = self_w[idx];
    if (threadIdx.x < 128) {
        int i = threadIdx.x;
        nbv[i] = node_b[i]; ngv[i] = node_g[i]; nbev[i] = node_be[i];
        sbv[i] = self_b[i]; sgv[i] = self_g[i]; sbev[i] = self_be[i];
    }
    __syncthreads();

    int unit = threadIdx.x >> 7;
    int t    = threadIdx.x & 127;
    int wu   = t >> 5;
    int lane = threadIdx.x & 31;
    int barid = unit + 1;
    float* U     = sm + 49920 + unit * 1568;
    float* flows = U;
    float* xns   = U + 1024;
    float* red   = U + 1536;

    int nG = (N_NODES + 3) >> 2;
    int gu = blockIdx.x * 4 + unit;
    int stride = gridDim.x * 4;

    for (int g = gu; g < nG; g += stride) {
        int base = g * 4;
        int nodes[4];
        bool valid[4];
        #pragma unroll
        for (int s = 0; s < 4; s++) {
            int n = base + s;
            valid[s] = n < N_NODES;
            nodes[s] = valid[s] ? n : 0;
        }
        #pragma unroll
        for (int pass = 0; pass < 8; pass++) {
            int idx = t + pass * 128;      // 0..1023
            int s = idx >> 8, j = idx & 255;
            flows[j * 4 + s] = g_flow[(size_t)nodes[s] * 256 + j];
        }
        #pragma unroll
        for (int pass = 0; pass < 4; pass++) {
            int idx = t + pass * 128;      // 0..511
            int s = idx >> 7, i = idx & 127;
            xns[i * 4 + s] = x[(size_t)nodes[s] * XW + i];
        }
        barSync(barid);

        float u0 = 0, u1 = 0, u2 = 0, u3 = 0;
        #pragma unroll 8
        for (int j = 0; j < 256; j++) {
            float4 fv = *reinterpret_cast<float4*>(&flows[j * 4]);
            float wv = nw[j * 128 + t];
            u0 += fv.x * wv; u1 += fv.y * wv; u2 += fv.z * wv; u3 += fv.w * wv;
        }
        float v0 = 0, v1 = 0, v2 = 0, v3 = 0;
        #pragma unroll 8
        for (int i = 0; i < 128; i++) {
            float4 xv = *reinterpret_cast<float4*>(&xns[i * 4]);
            float wv = sw[i * 128 + t];
            v0 += xv.x * wv; v1 += xv.y * wv; v2 += xv.z * wv; v3 += xv.w * wv;
        }
        float nb_ = nbv[t], sb_ = sbv[t];
        float uu[4] = { u0 + nb_, u1 + nb_, u2 + nb_, u3 + nb_ };
        float vv[4] = { v0 + sb_, v1 + sb_, v2 + sb_, v3 + sb_ };

        float sums[8] = { uu[0], uu[1], uu[2], uu[3], vv[0], vv[1], vv[2], vv[3] };
        ureduce<8>(sums, red, wu, lane, barid);
        float du[4], dv[4], sq[8];
        #pragma unroll
        for (int s = 0; s < 4; s++) {
            du[s] = uu[s] - sums[s] * (1.f / 128.f);
            dv[s] = vv[s] - sums[4 + s] * (1.f / 128.f);
            sq[s] = du[s] * du[s];
            sq[4 + s] = dv[s] * dv[s];
        }
        ureduce<8>(sq, red, wu, lane, barid);
        float ng_ = ngv[t], nbe_ = nbev[t], sg_ = sgv[t], sbe_ = sbev[t];
        #pragma unroll
        for (int s = 0; s < 4; s++) {
            float r1 = fmaxf(du[s] * rsqrtf(sq[s] * (1.f / 128.f) + LN_EPS) * ng_ + nbe_, 0.f);
            float r2 = fmaxf(dv[s] * rsqrtf(sq[4 + s] * (1.f / 128.f) + LN_EPS) * sg_ + sbe_, 0.f);
            if (valid[s]) out[(size_t)nodes[s] * XW + t] = r1 + r2;
        }
        if (t < 32) {
            #pragma unroll
            for (int s = 0; s < 4; s++) {
                if (valid[s])
                    out[(size_t)nodes[s] * XW + 128 + t] = x[(size_t)nodes[s] * XW + 128 + t];
            }
        }
    }
}

// ---------------- host ----------------
extern "C" void kernel_launch(void* const* d_in, const int* in_sizes, int n_in,
                              void* d_out, int out_size) {
    const float* x      = (const float*)d_in[0];
    const int*   ei     = (const int*)d_in[1];
    const float* eattr  = (const float*)d_in[2];
    const float* w_att  = (const float*)d_in[3];
    const float* b_att  = (const float*)d_in[4];
    const float* d2t_w1 = (const float*)d_in[5];
    const float* d2t_b1 = (const float*)d_in[6];
    const float* d2t_g1 = (const float*)d_in[7];
    const float* d2t_be1= (const float*)d_in[8];
    const float* d2t_w2 = (const float*)d_in[9];
    const float* d2t_b2 = (const float*)d_in[10];
    const float* d2t_g2 = (const float*)d_in[11];
    const float* d2t_be2= (const float*)d_in[12];
    const float* t2d_w1 = (const float*)d_in[13];
    const float* t2d_b1 = (const float*)d_in[14];
    const float* t2d_g1 = (const float*)d_in[15];
    const float* t2d_be1= (const float*)d_in[16];
    const float* t2d_w2 = (const float*)d_in[17];
    const float* t2d_b2 = (const float*)d_in[18];
    const float* t2d_g2 = (const float*)d_in[19];
    const float* t2d_be2= (const float*)d_in[20];
    const float* node_w = (const float*)d_in[21];
    const float* node_b = (const float*)d_in[22];
    const float* node_g = (const float*)d_in[23];
    const float* node_be= (const float*)d_in[24];
    const float* self_w = (const float*)d_in[25];
    const float* self_b = (const float*)d_in[26];
    const float* self_g = (const float*)d_in[27];
    const float* self_be= (const float*)d_in[28];
    float* out = (float*)d_out;

    const int EDGE_SMEM_BYTES  = EDGE_SMEM_FLOATS * 4;
    const int FINAL_SMEM_BYTES = FINAL_SMEM_FLOATS * 4;
    cudaFuncSetAttribute(k_edge,  cudaFuncAttributeMaxDynamicSharedMemorySize, EDGE_SMEM_BYTES);
    cudaFuncSetAttribute(k_final, cudaFuncAttributeMaxDynamicSharedMemorySize, FINAL_SMEM_BYTES);

    int initThreads = (int)((size_t)N_NODES * 256 / 4);
    k_init_att<<<(initThreads + 255) / 256, 256>>>(x, w_att);
    k_node_pre<<<(N_NODES + 15) / 16, 256>>>(x, d2t_w1, t2d_w1);
    k_sumexp<<<(N_EDGES + 255) / 256, 256>>>(ei, b_att);
    k_edge<<<148, 384, EDGE_SMEM_BYTES>>>(0, ei, eattr, d2t_w1,
        d2t_b1, d2t_g1, d2t_be1, d2t_w2, d2t_b2, d2t_g2, d2t_be2);
    k_edge<<<148, 384, EDGE_SMEM_BYTES>>>(1, ei, eattr, t2d_w1,
        t2d_b1, t2d_g1, t2d_be1, t2d_w2, t2d_b2, t2d_g2, t2d_be2);
    k_final<<<148, 512, FINAL_SMEM_BYTES>>>(x,
        node_w, node_b, node_g, node_be,
        self_w, self_b, self_g, self_be, out);
}

// round 5
// speedup vs baseline: 1.5478x; 1.4904x over previous
#include <cuda_runtime.h>
#include <cuda_bf16.h>
#include <math.h>
#include <stdint.h>

#define N_NODES 50000
#define N_EDGES 400000
#define D 128
#define H 256
#define EATTR 64
#define XW 160
#define LN_EPS 1e-5f
#define SLOPE 0.01f

__device__ float g_P0[(size_t)N_NODES * H];
__device__ float g_P1[(size_t)N_NODES * H];
__device__ float g_acol[N_NODES];
__device__ float g_arow[N_NODES];
__device__ float g_expv[N_EDGES];
__device__ int   g_elist0[N_EDGES];
__device__ int   g_elist1[N_EDGES];
__device__ float g_flow[(size_t)N_NODES * 256];
__device__ float g_h[(size_t)N_EDGES * 256];     // raw pre-LN hidden per edge
__device__ float g_dirsum[2];
__device__ int   g_ecnt[2];

__device__ __forceinline__ void barSync(int id) {
    asm volatile("bar.sync %0, %1;" :: "r"(id), "r"(128) : "memory");
}
template<int NV>
__device__ __forceinline__ void ureduce(float* v, float* red, int wu, int lane, int barid) {
    #pragma unroll
    for (int o = 16; o; o >>= 1) {
        #pragma unroll
        for (int k = 0; k < NV; k++) v[k] += __shfl_xor_sync(0xffffffffu, v[k], o);
    }
    if (lane == 0) {
        #pragma unroll
        for (int k = 0; k < NV; k++) red[wu * NV + k] = v[k];
    }
    barSync(barid);
    #pragma unroll
    for (int k = 0; k < NV; k++)
        v[k] = red[k] + red[NV + k] + red[2 * NV + k] + red[3 * NV + k];
    barSync(barid);
}

// bf16 hi/lo split of a pair of floats, packed low-half = first element
__device__ __forceinline__ void split2(float v0, float v1, uint32_t& hi, uint32_t& lo) {
    __nv_bfloat16 h0 = __float2bfloat16(v0), h1 = __float2bfloat16(v1);
    __nv_bfloat16 l0 = __float2bfloat16(v0 - __bfloat162float(h0));
    __nv_bfloat16 l1 = __float2bfloat16(v1 - __bfloat162float(h1));
    hi = ((uint32_t)__bfloat16_as_ushort(h1) << 16) | __bfloat16_as_ushort(h0);
    lo = ((uint32_t)__bfloat16_as_ushort(l1) << 16) | __bfloat16_as_ushort(l0);
}

__device__ __forceinline__ void mma_bf16(float* c, const uint4& a, const uint2& b) {
    asm volatile(
        "mma.sync.aligned.m16n8k16.row.col.f32.bf16.bf16.f32 "
        "{%0,%1,%2,%3}, {%4,%5,%6,%7}, {%8,%9}, {%0,%1,%2,%3};\n"
        : "+f"(c[0]), "+f"(c[1]), "+f"(c[2]), "+f"(c[3])
        : "r"(a.x), "r"(a.y), "r"(a.z), "r"(a.w), "r"(b.x), "r"(b.y));
}

// ---------------- prologue kernels (unchanged, passing) ----------------
__global__ void k_init_att(const float* __restrict__ x, const float* __restrict__ w_att) {
    size_t i = (size_t)blockIdx.x * blockDim.x + threadIdx.x;
    size_t n4 = (size_t)N_NODES * 256 / 4;
    if (i < n4) reinterpret_cast<float4*>(g_flow)[i] = make_float4(0.f, 0.f, 0.f, 0.f);
    if (i == 0) { g_dirsum[0] = 0.f; g_dirsum[1] = 0.f; g_ecnt[0] = 0; g_ecnt[1] = 0; }
    int gw = (int)(i >> 5);
    int lane = threadIdx.x & 31;
    if (gw < N_NODES) {
        const float* xr = x + (size_t)gw * XW;
        float s0 = 0.f, s1 = 0.f;
        #pragma unroll
        for (int k = lane; k < 128; k += 32) {
            float v = xr[k];
            s0 += v * w_att[k]; s1 += v * w_att[128 + k];
        }
        #pragma unroll
        for (int o = 16; o; o >>= 1) {
            s0 += __shfl_xor_sync(0xffffffffu, s0, o);
            s1 += __shfl_xor_sync(0xffffffffu, s1, o);
        }
        if (lane == 0) { g_acol[gw] = s0; g_arow[gw] = s1; }
    }
}

__global__ void k_node_pre(const float* __restrict__ x,
                           const float* __restrict__ w0, const float* __restrict__ w1) {
    __shared__ float xs[16 * 128];
    int nb = blockIdx.x * 16;
    for (int idx = threadIdx.x; idx < 16 * 128; idx += 256) {
        int nn = idx >> 7, i = idx & 127;
        int node = nb + nn;
        xs[idx] = (node < N_NODES) ? x[(size_t)node * XW + i] : 0.f;
    }
    __syncthreads();
    int j = threadIdx.x;
    for (int d = 0; d < 2; d++) {
        const float* W = d ? w1 : w0;
        float* P = d ? g_P1 : g_P0;
        float acc[16];
        #pragma unroll
        for (int n = 0; n < 16; n++) acc[n] = 0.f;
        for (int i = 0; i < 128; i += 4) {
            float wv0 = __ldg(&W[(size_t)(i + 0) * H + j]);
            float wv1 = __ldg(&W[(size_t)(i + 1) * H + j]);
            float wv2 = __ldg(&W[(size_t)(i + 2) * H + j]);
            float wv3 = __ldg(&W[(size_t)(i + 3) * H + j]);
            #pragma unroll
            for (int n = 0; n < 16; n++) {
                float4 xv = *reinterpret_cast<float4*>(&xs[n * 128 + i]);
                acc[n] += xv.x * wv0 + xv.y * wv1 + xv.z * wv2 + xv.w * wv3;
            }
        }
        #pragma unroll
        for (int n = 0; n < 16; n++) {
            int node = nb + n;
            if (node < N_NODES) P[(size_t)node * H + j] = acc[n];
        }
    }
}

__global__ void k_sumexp(const int* __restrict__ ei, const float* __restrict__ b_att) {
    __shared__ int c0, c1, base0, base1;
    __shared__ float rs0[8], rs1[8];
    if (threadIdx.x == 0) { c0 = 0; c1 = 0; }
    __syncthreads();
    int e = blockIdx.x * blockDim.x + threadIdx.x;
    int dir = -1, pos = 0;
    float ex = 0.f;
    if (e < N_EDGES) {
        int r = ei[e], c = ei[N_EDGES + e];
        if (r < c) dir = 0; else if (r > c) dir = 1;
        if (dir >= 0) {
            float z = g_acol[c] + g_arow[r] + b_att[0];
            float lg = z > 0.f ? z : SLOPE * z;
            ex = expf(lg);
            pos = atomicAdd(dir ? &c1 : &c0, 1);
        }
        g_expv[e] = ex;
    }
    float v0 = (dir == 0) ? ex : 0.f;
    float v1 = (dir == 1) ? ex : 0.f;
    #pragma unroll
    for (int o = 16; o; o >>= 1) {
        v0 += __shfl_xor_sync(0xffffffffu, v0, o);
        v1 += __shfl_xor_sync(0xffffffffu, v1, o);
    }
    int w = threadIdx.x >> 5, l = threadIdx.x & 31;
    if (l == 0) { rs0[w] = v0; rs1[w] = v1; }
    __syncthreads();
    if (threadIdx.x == 0) {
        float t0 = 0.f, t1 = 0.f;
        for (int k = 0; k < 8; k++) { t0 += rs0[k]; t1 += rs1[k]; }
        if (t0 != 0.f) atomicAdd(&g_dirsum[0], t0);
        if (t1 != 0.f) atomicAdd(&g_dirsum[1], t1);
        base0 = c0 ? atomicAdd(&g_ecnt[0], c0) : 0;
        base1 = c1 ? atomicAdd(&g_ecnt[1], c1) : 0;
    }
    __syncthreads();
    if (dir == 0) g_elist0[base0 + pos] = e;
    else if (dir == 1) g_elist1[base1 + pos] = e;
}

// ---------------- k_edge_g1: GEMM1 + h = attn*(P+D1)+b1 -> g_h ----------------
// smem offsets (bytes)
#define G1_EID   0
#define G1_COL   256
#define G1_ATT   512
#define G1_B1    1024
#define G1_A1H   2048
#define G1_A1L   10240
#define G1_W1H   18432
#define G1_W1L   51200
#define G1_PT    83968
#define P_STRIDE 260
#define SMEM_G1  (83968 + 64 * P_STRIDE * 4)   /* 150528 */

__global__ void __launch_bounds__(256, 1) k_edge_g1(
    int dir, const int* __restrict__ ei, const float* __restrict__ eattr,
    const float* __restrict__ w1full, const float* __restrict__ b1)
{
    extern __shared__ unsigned char smraw[];
    unsigned char* sm = smraw;
    int*   eidm  = (int*)(sm + G1_EID);
    int*   colm  = (int*)(sm + G1_COL);
    float* attnm = (float*)(sm + G1_ATT);
    float* b1s   = (float*)(sm + G1_B1);
    float* PTf   = (float*)(sm + G1_PT);

    int tid = threadIdx.x;
    int lane = tid & 31, wid = tid >> 5;
    int slot = wid & 3, half = wid >> 2;
    int gid = lane >> 2, tig = lane & 3;

    // stage W1bot fragments (hi/lo), paired along k
    const float* wbg = w1full + 128 * H;
    for (int idx = tid; idx < 8192; idx += 256) {
        int k2i = idx >> 8, n = idx & 255;
        int k = 2 * k2i;
        float v0 = wbg[(size_t)k * H + n];
        float v1 = wbg[(size_t)(k + 1) * H + n];
        uint32_t hi, lo; split2(v0, v1, hi, lo);
        int gn = n >> 3, ks = k >> 4;
        int lane_t = (n & 7) * 4 + ((k & 7) >> 1);
        int reg = (k & 15) >> 3;
        uint32_t off = ((uint32_t)(gn * 4 + ks) * 32 + lane_t) * 8 + reg * 4;
        *(uint32_t*)(sm + G1_W1H + off) = hi;
        *(uint32_t*)(sm + G1_W1L + off) = lo;
    }
    if (tid < 256) b1s[tid] = b1[tid];

    const int*   elist = dir ? g_elist1 : g_elist0;
    const float* Pd    = dir ? g_P1 : g_P0;
    int   cnt = g_ecnt[dir];
    float inv = 1.f / g_dirsum[dir];
    int nT = (cnt + 63) >> 6;
    __syncthreads();

    for (int tile = blockIdx.x; tile < nT; tile += gridDim.x) {
        if (tid < 64) {
            int li = tile * 64 + tid;
            bool valid = li < cnt;
            int ee = valid ? elist[li] : 0;
            eidm[tid]  = valid ? ee : -1;
            colm[tid]  = valid ? ei[N_EDGES + ee] : 0;
            attnm[tid] = valid ? g_expv[ee] * inv : 0.f;
        }
        __syncthreads();

        // stage A1 fragments + P tile: 8 rows per warp
        #pragma unroll
        for (int j = 0; j < 8; j++) {
            int r = wid * 8 + j;
            int e = eidm[r];
            int eC = e < 0 ? 0 : e;
            float2 v = *(const float2*)(eattr + (size_t)eC * EATTR + 2 * lane);
            uint32_t hi, lo; split2(v.x, v.y, hi, lo);
            int jr = r & 15;
            int lane_t = (jr & 7) * 4 + (lane & 3);
            int reg = (jr >> 3) | (((lane >> 2) & 1) << 1);
            int ks = lane >> 3;
            uint32_t off = ((uint32_t)((r >> 4) * 4 + ks) * 32 + lane_t) * 16 + reg * 4;
            *(uint32_t*)(sm + G1_A1H + off) = hi;
            *(uint32_t*)(sm + G1_A1L + off) = lo;
            const float4* pr = (const float4*)(Pd + (size_t)colm[r] * H);
            *(float4*)(PTf + r * P_STRIDE + 4 * lane)       = pr[lane];
            *(float4*)(PTf + r * P_STRIDE + 128 + 4 * lane) = pr[lane + 32];
        }
        __syncthreads();

        // GEMM1: warp = 16 edges x 128 cols (its half), K=64
        float acc[16][4];
        #pragma unroll
        for (int nt = 0; nt < 16; nt++)
            #pragma unroll
            for (int q = 0; q < 4; q++) acc[nt][q] = 0.f;
        #pragma unroll
        for (int ks = 0; ks < 4; ks++) {
            uint4 ah = *(const uint4*)(sm + G1_A1H + ((uint32_t)(slot * 4 + ks) * 32 + lane) * 16);
            uint4 al = *(const uint4*)(sm + G1_A1L + ((uint32_t)(slot * 4 + ks) * 32 + lane) * 16);
            #pragma unroll
            for (int nt = 0; nt < 16; nt++) {
                int gn = half * 16 + nt;
                uint2 bh = *(const uint2*)(sm + G1_W1H + ((uint32_t)(gn * 4 + ks) * 32 + lane) * 8);
                uint2 bl = *(const uint2*)(sm + G1_W1L + ((uint32_t)(gn * 4 + ks) * 32 + lane) * 8);
                mma_bf16(acc[nt], ah, bh);
                mma_bf16(acc[nt], al, bh);
                mma_bf16(acc[nt], ah, bl);
            }
        }

        // epilogue: h = attn*(P + D1) + b1 -> g_h
        int r0 = slot * 16 + gid, r1 = r0 + 8;
        float at0 = attnm[r0], at1 = attnm[r1];
        int e0 = eidm[r0], e1 = eidm[r1];
        #pragma unroll
        for (int nt = 0; nt < 16; nt++) {
            int c = half * 128 + nt * 8 + tig * 2;
            float b10 = b1s[c], b11 = b1s[c + 1];
            if (e0 >= 0) {
                float2 p0 = *(const float2*)(PTf + r0 * P_STRIDE + c);
                float2 hv = make_float2(at0 * (p0.x + acc[nt][0]) + b10,
                                        at0 * (p0.y + acc[nt][1]) + b11);
                *(float2*)(g_h + (size_t)e0 * 256 + c) = hv;
            }
            if (e1 >= 0) {
                float2 p1 = *(const float2*)(PTf + r1 * P_STRIDE + c);
                float2 hv = make_float2(at1 * (p1.x + acc[nt][2]) + b10,
                                        at1 * (p1.y + acc[nt][3]) + b11);
                *(float2*)(g_h + (size_t)e1 * 256 + c) = hv;
            }
        }
        __syncthreads();
    }
}

// ---------------- k_edge_g2: LN1+ReLU -> GEMM2 -> LN2+ReLU -> scatter ----------------
#define G2_EID   0
#define G2_ROW   256
#define G2_ST    512
#define G2_G1    1536
#define G2_BE1   2560
#define G2_B2    3584
#define G2_G2    4096
#define G2_BE2   4608
#define G2_A2H   5120
#define G2_A2L   37888
#define G2_W2H   70656
#define G2_W2L   136192
#define SMEM_G2  201728

__global__ void __launch_bounds__(256, 1) k_edge_g2(
    int dir, const int* __restrict__ ei,
    const float* __restrict__ g1, const float* __restrict__ be1,
    const float* __restrict__ w2, const float* __restrict__ b2,
    const float* __restrict__ g2, const float* __restrict__ be2)
{
    extern __shared__ unsigned char smraw[];
    unsigned char* sm = smraw;
    int*   eidm  = (int*)(sm + G2_EID);
    int*   rowsm = (int*)(sm + G2_ROW);
    float* statm = (float*)(sm + G2_ST);
    float* g1s   = (float*)(sm + G2_G1);
    float* be1s  = (float*)(sm + G2_BE1);
    float* b2s   = (float*)(sm + G2_B2);
    float* g2s   = (float*)(sm + G2_G2);
    float* be2s  = (float*)(sm + G2_BE2);

    int tid = threadIdx.x;
    int lane = tid & 31, wid = tid >> 5;
    int slot = wid & 3, nh = wid >> 2;
    int gid = lane >> 2, tig = lane & 3;

    // stage W2 fragments (hi/lo)
    for (int idx = tid; idx < 16384; idx += 256) {
        int k2i = idx >> 7, n = idx & 127;
        int k = 2 * k2i;
        float v0 = w2[(size_t)k * 128 + n];
        float v1 = w2[(size_t)(k + 1) * 128 + n];
        uint32_t hi, lo; split2(v0, v1, hi, lo);
        int gn = n >> 3, ks = k >> 4;
        int lane_t = (n & 7) * 4 + ((k & 7) >> 1);
        int reg = (k & 15) >> 3;
        uint32_t off = ((uint32_t)(gn * 16 + ks) * 32 + lane_t) * 8 + reg * 4;
        *(uint32_t*)(sm + G2_W2H + off) = hi;
        *(uint32_t*)(sm + G2_W2L + off) = lo;
    }
    if (tid < 256) { g1s[tid] = g1[tid]; be1s[tid] = be1[tid]; }
    if (tid < 128) { b2s[tid] = b2[tid]; g2s[tid] = g2[tid]; be2s[tid] = be2[tid]; }

    const int* elist = dir ? g_elist1 : g_elist0;
    int cnt = g_ecnt[dir];
    int off_n = dir ? 0 : 128;
    int nT = (cnt + 63) >> 6;
    __syncthreads();

    for (int tile = blockIdx.x; tile < nT; tile += gridDim.x) {
        if (tid < 64) {
            int li = tile * 64 + tid;
            bool valid = li < cnt;
            int ee = valid ? elist[li] : 0;
            eidm[tid]  = valid ? ee : 0;
            rowsm[tid] = valid ? ei[ee] : -1;
        }
        __syncthreads();

        // LN1 + ReLU + split -> A2 fragments (8 rows per warp, warp-local LN)
        #pragma unroll
        for (int j = 0; j < 8; j++) {
            int r = wid * 8 + j;
            const float4* hp = (const float4*)(g_h + (size_t)eidm[r] * 256);
            float4 va = hp[lane], vb = hp[lane + 32];
            float s = va.x + va.y + va.z + va.w + vb.x + vb.y + vb.z + vb.w;
            float q = va.x*va.x + va.y*va.y + va.z*va.z + va.w*va.w
                    + vb.x*vb.x + vb.y*vb.y + vb.z*vb.z + vb.w*vb.w;
            #pragma unroll
            for (int o = 16; o; o >>= 1) {
                s += __shfl_xor_sync(0xffffffffu, s, o);
                q += __shfl_xor_sync(0xffffffffu, q, o);
            }
            float mean = s * (1.f / 256.f);
            float var  = fmaxf(q * (1.f / 256.f) - mean * mean, 0.f);
            float rstd = rsqrtf(var + LN_EPS);
            int jr = r & 15, sl = r >> 4;
            const float* vv[2] = { (const float*)&va, (const float*)&vb };
            #pragma unroll
            for (int hvi = 0; hvi < 2; hvi++) {
                int kbase = hvi * 128 + 4 * lane;
                #pragma unroll
                for (int pr = 0; pr < 4; pr += 2) {
                    int k = kbase + pr;
                    float u0 = fmaxf((vv[hvi][pr]   - mean) * rstd * g1s[k]   + be1s[k],   0.f);
                    float u1 = fmaxf((vv[hvi][pr+1] - mean) * rstd * g1s[k+1] + be1s[k+1], 0.f);
                    uint32_t hi, lo; split2(u0, u1, hi, lo);
                    int ks = k >> 4, kk = k & 15;
                    int lane_t = (jr & 7) * 4 + ((kk & 7) >> 1);
                    int reg = (jr >> 3) | ((kk >> 3) << 1);
                    uint32_t off = ((uint32_t)(sl * 16 + ks) * 32 + lane_t) * 16 + reg * 4;
                    *(uint32_t*)(sm + G2_A2H + off) = hi;
                    *(uint32_t*)(sm + G2_A2L + off) = lo;
                }
            }
        }
        __syncthreads();

        // GEMM2: warp = 16 edges x 64 cols (its n-half), K=256
        float acc[8][4];
        #pragma unroll
        for (int nt = 0; nt < 8; nt++)
            #pragma unroll
            for (int q = 0; q < 4; q++) acc[nt][q] = 0.f;
        #pragma unroll
        for (int ks = 0; ks < 16; ks++) {
            uint4 ah = *(const uint4*)(sm + G2_A2H + ((uint32_t)(slot * 16 + ks) * 32 + lane) * 16);
            uint4 al = *(const uint4*)(sm + G2_A2L + ((uint32_t)(slot * 16 + ks) * 32 + lane) * 16);
            #pragma unroll
            for (int nt = 0; nt < 8; nt++) {
                int gn = nh * 8 + nt;
                uint2 bh = *(const uint2*)(sm + G2_W2H + ((uint32_t)(gn * 16 + ks) * 32 + lane) * 8);
                uint2 bl = *(const uint2*)(sm + G2_W2L + ((uint32_t)(gn * 16 + ks) * 32 + lane) * 8);
                mma_bf16(acc[nt], ah, bh);
                mma_bf16(acc[nt], al, bh);
                mma_bf16(acc[nt], ah, bl);
            }
        }

        // o = d + b2; partial LN2 stats (rows gid, gid+8 within warp's n-half)
        float sA = 0.f, qA = 0.f, sB = 0.f, qB = 0.f;
        #pragma unroll
        for (int nt = 0; nt < 8; nt++) {
            int c = nh * 64 + nt * 8 + tig * 2;
            acc[nt][0] += b2s[c];   acc[nt][1] += b2s[c + 1];
            acc[nt][2] += b2s[c];   acc[nt][3] += b2s[c + 1];
            sA += acc[nt][0] + acc[nt][1];
            qA += acc[nt][0]*acc[nt][0] + acc[nt][1]*acc[nt][1];
            sB += acc[nt][2] + acc[nt][3];
            qB += acc[nt][2]*acc[nt][2] + acc[nt][3]*acc[nt][3];
        }
        #pragma unroll
        for (int o = 1; o <= 2; o <<= 1) {
            sA += __shfl_xor_sync(0xffffffffu, sA, o);
            qA += __shfl_xor_sync(0xffffffffu, qA, o);
            sB += __shfl_xor_sync(0xffffffffu, sB, o);
            qB += __shfl_xor_sync(0xffffffffu, qB, o);
        }
        if (tig == 0) {
            int iA = ((slot * 16 + gid) * 2 + nh) * 2;
            int iB = ((slot * 16 + gid + 8) * 2 + nh) * 2;
            statm[iA] = sA; statm[iA + 1] = qA;
            statm[iB] = sB; statm[iB + 1] = qB;
        }
        __syncthreads();
        {
            int oA = ((slot * 16 + gid) * 2 + (nh ^ 1)) * 2;
            int oB = ((slot * 16 + gid + 8) * 2 + (nh ^ 1)) * 2;
            float tsA = sA + statm[oA], tqA = qA + statm[oA + 1];
            float tsB = sB + statm[oB], tqB = qB + statm[oB + 1];
            float mA = tsA * (1.f / 128.f);
            float rA_ = rsqrtf(fmaxf(tqA * (1.f / 128.f) - mA * mA, 0.f) + LN_EPS);
            float mB = tsB * (1.f / 128.f);
            float rB_ = rsqrtf(fmaxf(tqB * (1.f / 128.f) - mB * mB, 0.f) + LN_EPS);
            int rA = rowsm[slot * 16 + gid];
            int rB = rowsm[slot * 16 + gid + 8];
            #pragma unroll
            for (int nt = 0; nt < 8; nt++) {
                int c = nh * 64 + nt * 8 + tig * 2;
                if (rA >= 0) {
                    float v0 = fmaxf((acc[nt][0] - mA) * rA_ * g2s[c]     + be2s[c],     0.f);
                    float v1 = fmaxf((acc[nt][1] - mA) * rA_ * g2s[c + 1] + be2s[c + 1], 0.f);
                    atomicAdd(&g_flow[(size_t)rA * 256 + off_n + c],     v0);
                    atomicAdd(&g_flow[(size_t)rA * 256 + off_n + c + 1], v1);
                }
                if (rB >= 0) {
                    float v0 = fmaxf((acc[nt][2] - mB) * rB_ * g2s[c]     + be2s[c],     0.f);
                    float v1 = fmaxf((acc[nt][3] - mB) * rB_ * g2s[c + 1] + be2s[c + 1], 0.f);
                    atomicAdd(&g_flow[(size_t)rB * 256 + off_n + c],     v0);
                    atomicAdd(&g_flow[(size_t)rB * 256 + off_n + c + 1], v1);
                }
            }
        }
        __syncthreads();
    }
}

// ---------------- node finalize (unchanged, passing) ----------------
#define FINAL_SMEM_FLOATS (49920 + 4 * 1568)
__global__ void __launch_bounds__(512, 1) k_final(
    const float* __restrict__ x,
    const float* __restrict__ node_w, const float* __restrict__ node_b,
    const float* __restrict__ node_g, const float* __restrict__ node_be,
    const float* __restrict__ self_w, const float* __restrict__ self_b,
    const float* __restrict__ self_g, const float* __restrict__ self_be,
    float* __restrict__ out)
{
    extern __shared__ unsigned char smraw[];
    float* sm = (float*)smraw;
    float* nw = sm;
    float* sw = sm + 32768;
    float* nbv  = sm + 49152;
    float* ngv  = sm + 49280;
    float* nbev = sm + 49408;
    float* sbv  = sm + 49536;
    float* sgv  = sm + 49664;
    float* sbev = sm + 49792;
    for (int idx = threadIdx.x; idx < 32768; idx += 512) nw[idx] = node_w[idx];
    for (int idx = threadIdx.x; idx < 16384; idx += 512) sw[idx] = self_w[idx];
    if (threadIdx.x < 128) {
        int i = threadIdx.x;
        nbv[i] = node_b[i]; ngv[i] = node_g[i]; nbev[i] = node_be[i];
        sbv[i] = self_b[i]; sgv[i] = self_g[i]; sbev[i] = self_be[i];
    }
    __syncthreads();
    int unit = threadIdx.x >> 7;
    int t    = threadIdx.x & 127;
    int wu   = t >> 5;
    int lane = threadIdx.x & 31;
    int barid = unit + 1;
    float* U     = sm + 49920 + unit * 1568;
    float* flows = U;
    float* xns   = U + 1024;
    float* red   = U + 1536;
    int nG = (N_NODES + 3) >> 2;
    int gu = blockIdx.x * 4 + unit;
    int stride = gridDim.x * 4;
    for (int g = gu; g < nG; g += stride) {
        int base = g * 4;
        int nodes[4];
        bool valid[4];
        #pragma unroll
        for (int s = 0; s < 4; s++) {
            int n = base + s;
            valid[s] = n < N_NODES;
            nodes[s] = valid[s] ? n : 0;
        }
        #pragma unroll
        for (int pass = 0; pass < 8; pass++) {
            int idx = t + pass * 128;
            int s = idx >> 8, j = idx & 255;
            flows[j * 4 + s] = g_flow[(size_t)nodes[s] * 256 + j];
        }
        #pragma unroll
        for (int pass = 0; pass < 4; pass++) {
            int idx = t + pass * 128;
            int s = idx >> 7, i = idx & 127;
            xns[i * 4 + s] = x[(size_t)nodes[s] * XW + i];
        }
        barSync(barid);
        float u0 = 0, u1 = 0, u2 = 0, u3 = 0;
        #pragma unroll 8
        for (int j = 0; j < 256; j++) {
            float4 fv = *reinterpret_cast<float4*>(&flows[j * 4]);
            float wv = nw[j * 128 + t];
            u0 += fv.x * wv; u1 += fv.y * wv; u2 += fv.z * wv; u3 += fv.w * wv;
        }
        float v0 = 0, v1 = 0, v2 = 0, v3 = 0;
        #pragma unroll 8
        for (int i = 0; i < 128; i++) {
            float4 xv = *reinterpret_cast<float4*>(&xns[i * 4]);
            float wv = sw[i * 128 + t];
            v0 += xv.x * wv; v1 += xv.y * wv; v2 += xv.z * wv; v3 += xv.w * wv;
        }
        float nb_ = nbv[t], sb_ = sbv[t];
        float uu[4] = { u0 + nb_, u1 + nb_, u2 + nb_, u3 + nb_ };
        float vv[4] = { v0 + sb_, v1 + sb_, v2 + sb_, v3 + sb_ };
        float sums[8] = { uu[0], uu[1], uu[2], uu[3], vv[0], vv[1], vv[2], vv[3] };
        ureduce<8>(sums, red, wu, lane, barid);
        float du[4], dv[4], sq[8];
        #pragma unroll
        for (int s = 0; s < 4; s++) {
            du[s] = uu[s] - sums[s] * (1.f / 128.f);
            dv[s] = vv[s] - sums[4 + s] * (1.f / 128.f);
            sq[s] = du[s] * du[s];
            sq[4 + s] = dv[s] * dv[s];
        }
        ureduce<8>(sq, red, wu, lane, barid);
        float ng_ = ngv[t], nbe_ = nbev[t], sg_ = sgv[t], sbe_ = sbev[t];
        #pragma unroll
        for (int s = 0; s < 4; s++) {
            float r1 = fmaxf(du[s] * rsqrtf(sq[s] * (1.f / 128.f) + LN_EPS) * ng_ + nbe_, 0.f);
            float r2 = fmaxf(dv[s] * rsqrtf(sq[4 + s] * (1.f / 128.f) + LN_EPS) * sg_ + sbe_, 0.f);
            if (valid[s]) out[(size_t)nodes[s] * XW + t] = r1 + r2;
        }
        if (t < 32) {
            #pragma unroll
            for (int s = 0; s < 4; s++)
                if (valid[s])
                    out[(size_t)nodes[s] * XW + 128 + t] = x[(size_t)nodes[s] * XW + 128 + t];
        }
    }
}

extern "C" void kernel_launch(void* const* d_in, const int* in_sizes, int n_in,
                              void* d_out, int out_size) {
    const float* x      = (const float*)d_in[0];
    const int*   ei     = (const int*)d_in[1];
    const float* eattr  = (const float*)d_in[2];
    const float* w_att  = (const float*)d_in[3];
    const float* b_att  = (const float*)d_in[4];
    const float* d2t_w1 = (const float*)d_in[5];
    const float* d2t_b1 = (const float*)d_in[6];
    const float* d2t_g1 = (const float*)d_in[7];
    const float* d2t_be1= (const float*)d_in[8];
    const float* d2t_w2 = (const float*)d_in[9];
    const float* d2t_b2 = (const float*)d_in[10];
    const float* d2t_g2 = (const float*)d_in[11];
    const float* d2t_be2= (const float*)d_in[12];
    const float* t2d_w1 = (const float*)d_in[13];
    const float* t2d_b1 = (const float*)d_in[14];
    const float* t2d_g1 = (const float*)d_in[15];
    const float* t2d_be1= (const float*)d_in[16];
    const float* t2d_w2 = (const float*)d_in[17];
    const float* t2d_b2 = (const float*)d_in[18];
    const float* t2d_g2 = (const float*)d_in[19];
    const float* t2d_be2= (const float*)d_in[20];
    const float* node_w = (const float*)d_in[21];
    const float* node_b = (const float*)d_in[22];
    const float* node_g = (const float*)d_in[23];
    const float* node_be= (const float*)d_in[24];
    const float* self_w = (const float*)d_in[25];
    const float* self_b = (const float*)d_in[26];
    const float* self_g = (const float*)d_in[27];
    const float* self_be= (const float*)d_in[28];
    float* out = (float*)d_out;

    const int FINAL_SMEM_BYTES = FINAL_SMEM_FLOATS * 4;
    cudaFuncSetAttribute(k_edge_g1, cudaFuncAttributeMaxDynamicSharedMemorySize, SMEM_G1);
    cudaFuncSetAttribute(k_edge_g2, cudaFuncAttributeMaxDynamicSharedMemorySize, SMEM_G2);
    cudaFuncSetAttribute(k_final,   cudaFuncAttributeMaxDynamicSharedMemorySize, FINAL_SMEM_BYTES);

    int initThreads = (int)((size_t)N_NODES * 256 / 4);
    k_init_att<<<(initThreads + 255) / 256, 256>>>(x, w_att);
    k_node_pre<<<(N_NODES + 15) / 16, 256>>>(x, d2t_w1, t2d_w1);
    k_sumexp<<<(N_EDGES + 255) / 256, 256>>>(ei, b_att);
    k_edge_g1<<<148, 256, SMEM_G1>>>(0, ei, eattr, d2t_w1, d2t_b1);
    k_edge_g1<<<148, 256, SMEM_G1>>>(1, ei, eattr, t2d_w1, t2d_b1);
    k_edge_g2<<<148, 256, SMEM_G2>>>(0, ei, d2t_g1, d2t_be1, d2t_w2, d2t_b2, d2t_g2, d2t_be2);
    k_edge_g2<<<148, 256, SMEM_G2>>>(1, ei, t2d_g1, t2d_be1, t2d_w2, t2d_b2, t2d_g2, t2d_be2);
    k_final<<<148, 512, FINAL_SMEM_BYTES>>>(x,
        node_w, node_b, node_g, node_be,
        self_w, self_b, self_g, self_be, out);
}

// round 6
// speedup vs baseline: 2.4760x; 1.5997x over previous
#include <cuda_runtime.h>
#include <cuda_bf16.h>
#include <math.h>
#include <stdint.h>

#define N_NODES 50000
#define N_EDGES 400000
#define D 128
#define H 256
#define EATTR 64
#define XW 160
#define LN_EPS 1e-5f
#define SLOPE 0.01f
#define MAXT 6252   /* max 64-edge tiles per direction */

__device__ float g_P0[(size_t)N_NODES * H];
__device__ float g_P1[(size_t)N_NODES * H];
__device__ float g_acol[N_NODES];
__device__ float g_arow[N_NODES];
__device__ float g_expv[N_EDGES];
__device__ int   g_elist0[N_EDGES];
__device__ int   g_elist1[N_EDGES];
__device__ float g_flow[(size_t)N_NODES * 256];
__device__ uint4 g_hf4[(size_t)2 * MAXT * 4096];  // per tile: 2048 uint4 hi + 2048 lo
__device__ float g_dirsum[2];
__device__ int   g_ecnt[2];

__device__ __forceinline__ void barSync(int id) {
    asm volatile("bar.sync %0, %1;" :: "r"(id), "r"(128) : "memory");
}
template<int NV>
__device__ __forceinline__ void ureduce(float* v, float* red, int wu, int lane, int barid) {
    #pragma unroll
    for (int o = 16; o; o >>= 1) {
        #pragma unroll
        for (int k = 0; k < NV; k++) v[k] += __shfl_xor_sync(0xffffffffu, v[k], o);
    }
    if (lane == 0) {
        #pragma unroll
        for (int k = 0; k < NV; k++) red[wu * NV + k] = v[k];
    }
    barSync(barid);
    #pragma unroll
    for (int k = 0; k < NV; k++)
        v[k] = red[k] + red[NV + k] + red[2 * NV + k] + red[3 * NV + k];
    barSync(barid);
}

__device__ __forceinline__ void split2(float v0, float v1, uint32_t& hi, uint32_t& lo) {
    __nv_bfloat16 h0 = __float2bfloat16(v0), h1 = __float2bfloat16(v1);
    __nv_bfloat16 l0 = __float2bfloat16(v0 - __bfloat162float(h0));
    __nv_bfloat16 l1 = __float2bfloat16(v1 - __bfloat162float(h1));
    hi = ((uint32_t)__bfloat16_as_ushort(h1) << 16) | __bfloat16_as_ushort(h0);
    lo = ((uint32_t)__bfloat16_as_ushort(l1) << 16) | __bfloat16_as_ushort(l0);
}

__device__ __forceinline__ void mma_bf16(float* c, const uint4& a, const uint2& b) {
    asm volatile(
        "mma.sync.aligned.m16n8k16.row.col.f32.bf16.bf16.f32 "
        "{%0,%1,%2,%3}, {%4,%5,%6,%7}, {%8,%9}, {%0,%1,%2,%3};\n"
        : "+f"(c[0]), "+f"(c[1]), "+f"(c[2]), "+f"(c[3])
        : "r"(a.x), "r"(a.y), "r"(a.z), "r"(a.w), "r"(b.x), "r"(b.y));
}

// ---------------- prologue ----------------
__global__ void k_init_att(const float* __restrict__ x, const float* __restrict__ w_att) {
    size_t i = (size_t)blockIdx.x * blockDim.x + threadIdx.x;
    size_t n4 = (size_t)N_NODES * 256 / 4;
    if (i < n4) reinterpret_cast<float4*>(g_flow)[i] = make_float4(0.f, 0.f, 0.f, 0.f);
    if (i == 0) { g_dirsum[0] = 0.f; g_dirsum[1] = 0.f; g_ecnt[0] = 0; g_ecnt[1] = 0; }
    int gw = (int)(i >> 5);
    int lane = threadIdx.x & 31;
    if (gw < N_NODES) {
        const float* xr = x + (size_t)gw * XW;
        float s0 = 0.f, s1 = 0.f;
        #pragma unroll
        for (int k = lane; k < 128; k += 32) {
            float v = xr[k];
            s0 += v * w_att[k]; s1 += v * w_att[128 + k];
        }
        #pragma unroll
        for (int o = 16; o; o >>= 1) {
            s0 += __shfl_xor_sync(0xffffffffu, s0, o);
            s1 += __shfl_xor_sync(0xffffffffu, s1, o);
        }
        if (lane == 0) { g_acol[gw] = s0; g_arow[gw] = s1; }
    }
}

__global__ void k_sumexp(const int* __restrict__ ei, const float* __restrict__ b_att) {
    __shared__ int c0, c1, base0, base1;
    __shared__ float rs0[8], rs1[8];
    if (threadIdx.x == 0) { c0 = 0; c1 = 0; }
    __syncthreads();
    int e = blockIdx.x * blockDim.x + threadIdx.x;
    int dir = -1, pos = 0;
    float ex = 0.f;
    if (e < N_EDGES) {
        int r = ei[e], c = ei[N_EDGES + e];
        if (r < c) dir = 0; else if (r > c) dir = 1;
        if (dir >= 0) {
            float z = g_acol[c] + g_arow[r] + b_att[0];
            float lg = z > 0.f ? z : SLOPE * z;
            ex = expf(lg);
            pos = atomicAdd(dir ? &c1 : &c0, 1);
        }
        g_expv[e] = ex;
    }
    float v0 = (dir == 0) ? ex : 0.f;
    float v1 = (dir == 1) ? ex : 0.f;
    #pragma unroll
    for (int o = 16; o; o >>= 1) {
        v0 += __shfl_xor_sync(0xffffffffu, v0, o);
        v1 += __shfl_xor_sync(0xffffffffu, v1, o);
    }
    int w = threadIdx.x >> 5, l = threadIdx.x & 31;
    if (l == 0) { rs0[w] = v0; rs1[w] = v1; }
    __syncthreads();
    if (threadIdx.x == 0) {
        float t0 = 0.f, t1 = 0.f;
        for (int k = 0; k < 8; k++) { t0 += rs0[k]; t1 += rs1[k]; }
        if (t0 != 0.f) atomicAdd(&g_dirsum[0], t0);
        if (t1 != 0.f) atomicAdd(&g_dirsum[1], t1);
        base0 = c0 ? atomicAdd(&g_ecnt[0], c0) : 0;
        base1 = c1 ? atomicAdd(&g_ecnt[1], c1) : 0;
    }
    __syncthreads();
    if (dir == 0) g_elist0[base0 + pos] = e;
    else if (dir == 1) g_elist1[base1 + pos] = e;
}

// ---------------- tensorized node precompute: P = xn @ W1top (both dirs) ----------------
#define NM_AH 0
#define NM_AL 16384
#define NM_WH 32768
#define NM_WL 98304
#define SMEM_NM 163840

__global__ void __launch_bounds__(256, 1) k_node_mma(
    const float* __restrict__ x, const float* __restrict__ w0, const float* __restrict__ w1)
{
    extern __shared__ unsigned char sm[];
    int tid = threadIdx.x;
    int lane = tid & 31, wid = tid >> 5;
    int slot = wid & 3, nh = wid >> 2;
    int gid = lane >> 2, tig = lane & 3;

    for (int d = 0; d < 2; d++) {
        const float* W = d ? w1 : w0;
        float* P = d ? g_P1 : g_P0;
        __syncthreads();
        for (int idx = tid; idx < 16384; idx += 256) {
            int k2i = idx >> 8, n = idx & 255;
            int k = 2 * k2i;
            float v0 = W[(size_t)k * H + n], v1 = W[(size_t)(k + 1) * H + n];
            uint32_t hi, lo; split2(v0, v1, hi, lo);
            int gn = n >> 3, ks = k >> 4;
            int lane_t = (n & 7) * 4 + ((k & 7) >> 1);
            int reg = (k & 15) >> 3;
            uint32_t off = ((uint32_t)(gn * 8 + ks) * 32 + lane_t) * 8 + reg * 4;
            *(uint32_t*)(sm + NM_WH + off) = hi;
            *(uint32_t*)(sm + NM_WL + off) = lo;
        }
        __syncthreads();
        int nTn = (N_NODES + 63) >> 6;
        for (int tile = blockIdx.x; tile < nTn; tile += gridDim.x) {
            #pragma unroll
            for (int j = 0; j < 8; j++) {
                int r = wid * 8 + j;
                int node = tile * 64 + r;
                int nodeC = node < N_NODES ? node : 0;
                int jr = r & 15, sl = r >> 4;
                #pragma unroll
                for (int kh = 0; kh < 2; kh++) {
                    float2 v = *(const float2*)(x + (size_t)nodeC * XW + kh * 64 + 2 * lane);
                    uint32_t hi, lo; split2(v.x, v.y, hi, lo);
                    int lane_t = (jr & 7) * 4 + (lane & 3);
                    int reg = (jr >> 3) | (((lane >> 2) & 1) << 1);
                    int ks = kh * 4 + (lane >> 3);
                    uint32_t off = ((uint32_t)(sl * 8 + ks) * 32 + lane_t) * 16 + reg * 4;
                    *(uint32_t*)(sm + NM_AH + off) = hi;
                    *(uint32_t*)(sm + NM_AL + off) = lo;
                }
            }
            __syncthreads();
            float acc[16][4];
            #pragma unroll
            for (int nt = 0; nt < 16; nt++)
                #pragma unroll
                for (int q = 0; q < 4; q++) acc[nt][q] = 0.f;
            #pragma unroll
            for (int ks = 0; ks < 8; ks++) {
                uint4 ah = *(const uint4*)(sm + NM_AH + ((uint32_t)(slot * 8 + ks) * 32 + lane) * 16);
                uint4 al = *(const uint4*)(sm + NM_AL + ((uint32_t)(slot * 8 + ks) * 32 + lane) * 16);
                #pragma unroll
                for (int nt = 0; nt < 16; nt++) {
                    int gn = nh * 16 + nt;
                    uint2 bh = *(const uint2*)(sm + NM_WH + ((uint32_t)(gn * 8 + ks) * 32 + lane) * 8);
                    uint2 bl = *(const uint2*)(sm + NM_WL + ((uint32_t)(gn * 8 + ks) * 32 + lane) * 8);
                    mma_bf16(acc[nt], ah, bh);
                    mma_bf16(acc[nt], al, bh);
                    mma_bf16(acc[nt], ah, bl);
                }
            }
            int r0 = slot * 16 + gid, r1 = r0 + 8;
            int n0 = tile * 64 + r0, n1 = tile * 64 + r1;
            #pragma unroll
            for (int nt = 0; nt < 16; nt++) {
                int c = nh * 128 + nt * 8 + tig * 2;
                if (n0 < N_NODES) *(float2*)(P + (size_t)n0 * H + c) = make_float2(acc[nt][0], acc[nt][1]);
                if (n1 < N_NODES) *(float2*)(P + (size_t)n1 * H + c) = make_float2(acc[nt][2], acc[nt][3]);
            }
            __syncthreads();
        }
    }
}

// ---------------- k_edge_g1: GEMM1 + h=attn*(P+D1)+b1 + LN1 + ReLU -> bf16 frags ----------------
#define G1_EID   0
#define G1_COL   256
#define G1_ATT   512
#define G1_ST    768
#define G1_B1    1792
#define G1_G1    2816
#define G1_BE1   3840
#define G1_A1H   4864
#define G1_A1L   13056
#define G1_W1H   21248
#define G1_W1L   54016
#define SMEM_G1  86784

__global__ void __launch_bounds__(256, 2) k_edge_g1(
    int dir, const int* __restrict__ ei, const float* __restrict__ eattr,
    const float* __restrict__ w1full, const float* __restrict__ b1,
    const float* __restrict__ g1v, const float* __restrict__ be1v)
{
    extern __shared__ unsigned char sm[];
    int*   eidm  = (int*)(sm + G1_EID);
    int*   colm  = (int*)(sm + G1_COL);
    float* attnm = (float*)(sm + G1_ATT);
    float* statm = (float*)(sm + G1_ST);
    float* b1s   = (float*)(sm + G1_B1);
    float* g1s   = (float*)(sm + G1_G1);
    float* be1s  = (float*)(sm + G1_BE1);

    int tid = threadIdx.x;
    int lane = tid & 31, wid = tid >> 5;
    int slot = wid & 3, half = wid >> 2;
    int gid = lane >> 2, tig = lane & 3;

    const float* wbg = w1full + 128 * H;
    for (int idx = tid; idx < 8192; idx += 256) {
        int k2i = idx >> 8, n = idx & 255;
        int k = 2 * k2i;
        float v0 = wbg[(size_t)k * H + n], v1 = wbg[(size_t)(k + 1) * H + n];
        uint32_t hi, lo; split2(v0, v1, hi, lo);
        int gn = n >> 3, ks = k >> 4;
        int lane_t = (n & 7) * 4 + ((k & 7) >> 1);
        int reg = (k & 15) >> 3;
        uint32_t off = ((uint32_t)(gn * 4 + ks) * 32 + lane_t) * 8 + reg * 4;
        *(uint32_t*)(sm + G1_W1H + off) = hi;
        *(uint32_t*)(sm + G1_W1L + off) = lo;
    }
    b1s[tid]  = b1[tid];
    g1s[tid]  = g1v[tid];
    be1s[tid] = be1v[tid];

    const int*   elist = dir ? g_elist1 : g_elist0;
    const float* Pd    = dir ? g_P1 : g_P0;
    int   cnt = g_ecnt[dir];
    float inv = 1.f / g_dirsum[dir];
    int nT = (cnt + 63) >> 6;
    __syncthreads();

    for (int tile = blockIdx.x; tile < nT; tile += gridDim.x) {
        if (tid < 64) {
            int li = tile * 64 + tid;
            bool valid = li < cnt;
            int ee = valid ? elist[li] : 0;
            eidm[tid]  = valid ? ee : -1;
            colm[tid]  = valid ? ei[N_EDGES + ee] : 0;
            attnm[tid] = valid ? g_expv[ee] * inv : 0.f;
        }
        __syncthreads();

        #pragma unroll
        for (int j = 0; j < 8; j++) {
            int r = wid * 8 + j;
            int e = eidm[r];
            int eC = e < 0 ? 0 : e;
            float2 v = *(const float2*)(eattr + (size_t)eC * EATTR + 2 * lane);
            uint32_t hi, lo; split2(v.x, v.y, hi, lo);
            int jr = r & 15;
            int lane_t = (jr & 7) * 4 + (lane & 3);
            int reg = (jr >> 3) | (((lane >> 2) & 1) << 1);
            int ks = lane >> 3;
            uint32_t off = ((uint32_t)((r >> 4) * 4 + ks) * 32 + lane_t) * 16 + reg * 4;
            *(uint32_t*)(sm + G1_A1H + off) = hi;
            *(uint32_t*)(sm + G1_A1L + off) = lo;
        }
        __syncthreads();

        float acc[16][4];
        #pragma unroll
        for (int nt = 0; nt < 16; nt++)
            #pragma unroll
            for (int q = 0; q < 4; q++) acc[nt][q] = 0.f;
        #pragma unroll
        for (int ks = 0; ks < 4; ks++) {
            uint4 ah = *(const uint4*)(sm + G1_A1H + ((uint32_t)(slot * 4 + ks) * 32 + lane) * 16);
            uint4 al = *(const uint4*)(sm + G1_A1L + ((uint32_t)(slot * 4 + ks) * 32 + lane) * 16);
            #pragma unroll
            for (int nt = 0; nt < 16; nt++) {
                int gn = half * 16 + nt;
                uint2 bh = *(const uint2*)(sm + G1_W1H + ((uint32_t)(gn * 4 + ks) * 32 + lane) * 8);
                uint2 bl = *(const uint2*)(sm + G1_W1L + ((uint32_t)(gn * 4 + ks) * 32 + lane) * 8);
                mma_bf16(acc[nt], ah, bh);
                mma_bf16(acc[nt], al, bh);
                mma_bf16(acc[nt], ah, bl);
            }
        }

        // h = attn*(P + D1) + b1 (in place), LN1 stats
        int r0 = slot * 16 + gid, r1 = r0 + 8;
        float at0 = attnm[r0], at1 = attnm[r1];
        const float* P0 = Pd + (size_t)colm[r0] * H;
        const float* P1 = Pd + (size_t)colm[r1] * H;
        float sA = 0.f, qA = 0.f, sB = 0.f, qB = 0.f;
        #pragma unroll
        for (int nt = 0; nt < 16; nt++) {
            int c = half * 128 + nt * 8 + tig * 2;
            float2 p0 = *(const float2*)(P0 + c);
            float2 p1 = *(const float2*)(P1 + c);
            float b10 = b1s[c], b11 = b1s[c + 1];
            acc[nt][0] = at0 * (p0.x + acc[nt][0]) + b10;
            acc[nt][1] = at0 * (p0.y + acc[nt][1]) + b11;
            acc[nt][2] = at1 * (p1.x + acc[nt][2]) + b10;
            acc[nt][3] = at1 * (p1.y + acc[nt][3]) + b11;
            sA += acc[nt][0] + acc[nt][1];
            qA += acc[nt][0] * acc[nt][0] + acc[nt][1] * acc[nt][1];
            sB += acc[nt][2] + acc[nt][3];
            qB += acc[nt][2] * acc[nt][2] + acc[nt][3] * acc[nt][3];
        }
        #pragma unroll
        for (int o = 1; o <= 2; o <<= 1) {
            sA += __shfl_xor_sync(0xffffffffu, sA, o);
            qA += __shfl_xor_sync(0xffffffffu, qA, o);
            sB += __shfl_xor_sync(0xffffffffu, sB, o);
            qB += __shfl_xor_sync(0xffffffffu, qB, o);
        }
        if (tig == 0) {
            statm[(r0 * 2 + half) * 2]     = sA;
            statm[(r0 * 2 + half) * 2 + 1] = qA;
            statm[(r1 * 2 + half) * 2]     = sB;
            statm[(r1 * 2 + half) * 2 + 1] = qB;
        }
        __syncthreads();
        float sTA = sA + statm[(r0 * 2 + (half ^ 1)) * 2];
        float qTA = qA + statm[(r0 * 2 + (half ^ 1)) * 2 + 1];
        float sTB = sB + statm[(r1 * 2 + (half ^ 1)) * 2];
        float qTB = qB + statm[(r1 * 2 + (half ^ 1)) * 2 + 1];
        float mA = sTA * (1.f / 256.f);
        float rA = rsqrtf(fmaxf(qTA * (1.f / 256.f) - mA * mA, 0.f) + LN_EPS);
        float mB = sTB * (1.f / 256.f);
        float rB = rsqrtf(fmaxf(qTB * (1.f / 256.f) - mB * mB, 0.f) + LN_EPS);

        uint2* hf2 = (uint2*)(g_hf4 + (size_t)(dir * MAXT + tile) * 4096);
        #pragma unroll
        for (int nt = 0; nt < 16; nt++) {
            int c = half * 128 + nt * 8 + tig * 2;
            float u0 = fmaxf((acc[nt][0] - mA) * rA * g1s[c]     + be1s[c],     0.f);
            float u1 = fmaxf((acc[nt][1] - mA) * rA * g1s[c + 1] + be1s[c + 1], 0.f);
            float w0 = fmaxf((acc[nt][2] - mB) * rB * g1s[c]     + be1s[c],     0.f);
            float w1 = fmaxf((acc[nt][3] - mB) * rB * g1s[c + 1] + be1s[c + 1], 0.f);
            uint32_t hiA, loA, hiB, loB;
            split2(u0, u1, hiA, loA);
            split2(w0, w1, hiB, loB);
            int ks = half * 8 + (nt >> 1);
            uint32_t g = (uint32_t)(slot * 16 + ks) * 32 + lane;
            hf2[g * 2 + (nt & 1)]        = make_uint2(hiA, hiB);
            hf2[4096 + g * 2 + (nt & 1)] = make_uint2(loA, loB);
        }
        __syncthreads();
    }
}

// ---------------- k_edge_g2: GEMM2 (A frags from gmem) + LN2 + ReLU + scatter ----------------
#define G2_ST    0
#define G2_B2    2048
#define G2_G2    2560
#define G2_BE2   3072
#define G2_W2H   3584
#define G2_W2L   69120
#define SMEM_G2  134656

__global__ void __launch_bounds__(512, 1) k_edge_g2(
    int dir, const int* __restrict__ ei,
    const float* __restrict__ w2, const float* __restrict__ b2,
    const float* __restrict__ g2v, const float* __restrict__ be2v)
{
    extern __shared__ unsigned char sm[];
    float* statm = (float*)(sm + G2_ST);
    float* b2s   = (float*)(sm + G2_B2);
    float* g2s   = (float*)(sm + G2_G2);
    float* be2s  = (float*)(sm + G2_BE2);

    int tid = threadIdx.x;
    int lane = tid & 31, wid = tid >> 5;
    int slot = wid & 3, nh = wid >> 2;   // nh 0..3: 32-col quarter
    int gid = lane >> 2, tig = lane & 3;

    for (int idx = tid; idx < 16384; idx += 512) {
        int k2i = idx >> 7, n = idx & 127;
        int k = 2 * k2i;
        float v0 = w2[(size_t)k * 128 + n], v1 = w2[(size_t)(k + 1) * 128 + n];
        uint32_t hi, lo; split2(v0, v1, hi, lo);
        int gn = n >> 3, ks = k >> 4;
        int lane_t = (n & 7) * 4 + ((k & 7) >> 1);
        int reg = (k & 15) >> 3;
        uint32_t off = ((uint32_t)(gn * 16 + ks) * 32 + lane_t) * 8 + reg * 4;
        *(uint32_t*)(sm + G2_W2H + off) = hi;
        *(uint32_t*)(sm + G2_W2L + off) = lo;
    }
    if (tid < 128) { b2s[tid] = b2[tid]; g2s[tid] = g2v[tid]; be2s[tid] = be2v[tid]; }

    const int* elist = dir ? g_elist1 : g_elist0;
    int cnt = g_ecnt[dir];
    int off_n = dir ? 0 : 128;
    int nT = (cnt + 63) >> 6;
    __syncthreads();

    for (int tile = blockIdx.x; tile < nT; tile += gridDim.x) {
        int liA = tile * 64 + slot * 16 + gid;
        int liB = liA + 8;
        int rA = (liA < cnt) ? ei[elist[liA]] : -1;
        int rB = (liB < cnt) ? ei[elist[liB]] : -1;

        const uint4* hf4 = g_hf4 + (size_t)(dir * MAXT + tile) * 4096;
        float acc[4][4];
        #pragma unroll
        for (int nt = 0; nt < 4; nt++)
            #pragma unroll
            for (int q = 0; q < 4; q++) acc[nt][q] = 0.f;
        #pragma unroll
        for (int ks = 0; ks < 16; ks++) {
            uint32_t g = (uint32_t)(slot * 16 + ks) * 32 + lane;
            uint4 ah = hf4[g];
            uint4 al = hf4[2048 + g];
            #pragma unroll
            for (int nt = 0; nt < 4; nt++) {
                int gn = nh * 4 + nt;
                uint2 bh = *(const uint2*)(sm + G2_W2H + ((uint32_t)(gn * 16 + ks) * 32 + lane) * 8);
                uint2 bl = *(const uint2*)(sm + G2_W2L + ((uint32_t)(gn * 16 + ks) * 32 + lane) * 8);
                mma_bf16(acc[nt], ah, bh);
                mma_bf16(acc[nt], al, bh);
                mma_bf16(acc[nt], ah, bl);
            }
        }

        float sA = 0.f, qA = 0.f, sB = 0.f, qB = 0.f;
        #pragma unroll
        for (int nt = 0; nt < 4; nt++) {
            int c = nh * 32 + nt * 8 + tig * 2;
            acc[nt][0] += b2s[c];   acc[nt][1] += b2s[c + 1];
            acc[nt][2] += b2s[c];   acc[nt][3] += b2s[c + 1];
            sA += acc[nt][0] + acc[nt][1];
            qA += acc[nt][0] * acc[nt][0] + acc[nt][1] * acc[nt][1];
            sB += acc[nt][2] + acc[nt][3];
            qB += acc[nt][2] * acc[nt][2] + acc[nt][3] * acc[nt][3];
        }
        #pragma unroll
        for (int o = 1; o <= 2; o <<= 1) {
            sA += __shfl_xor_sync(0xffffffffu, sA, o);
            qA += __shfl_xor_sync(0xffffffffu, qA, o);
            sB += __shfl_xor_sync(0xffffffffu, sB, o);
            qB += __shfl_xor_sync(0xffffffffu, qB, o);
        }
        int e0 = slot * 16 + gid, e1 = e0 + 8;
        if (tig == 0) {
            statm[(e0 * 4 + nh) * 2]     = sA;
            statm[(e0 * 4 + nh) * 2 + 1] = qA;
            statm[(e1 * 4 + nh) * 2]     = sB;
            statm[(e1 * 4 + nh) * 2 + 1] = qB;
        }
        __syncthreads();
        float sTA = 0.f, qTA = 0.f, sTB = 0.f, qTB = 0.f;
        #pragma unroll
        for (int h = 0; h < 4; h++) {
            sTA += statm[(e0 * 4 + h) * 2];  qTA += statm[(e0 * 4 + h) * 2 + 1];
            sTB += statm[(e1 * 4 + h) * 2];  qTB += statm[(e1 * 4 + h) * 2 + 1];
        }
        float mA = sTA * (1.f / 128.f);
        float rAi = rsqrtf(fmaxf(qTA * (1.f / 128.f) - mA * mA, 0.f) + LN_EPS);
        float mB = sTB * (1.f / 128.f);
        float rBi = rsqrtf(fmaxf(qTB * (1.f / 128.f) - mB * mB, 0.f) + LN_EPS);
        #pragma unroll
        for (int nt = 0; nt < 4; nt++) {
            int c = nh * 32 + nt * 8 + tig * 2;
            if (rA >= 0) {
                float v0 = fmaxf((acc[nt][0] - mA) * rAi * g2s[c]     + be2s[c],     0.f);
                float v1 = fmaxf((acc[nt][1] - mA) * rAi * g2s[c + 1] + be2s[c + 1], 0.f);
                atomicAdd(&g_flow[(size_t)rA * 256 + off_n + c],     v0);
                atomicAdd(&g_flow[(size_t)rA * 256 + off_n + c + 1], v1);
            }
            if (rB >= 0) {
                float v0 = fmaxf((acc[nt][2] - mB) * rBi * g2s[c]     + be2s[c],     0.f);
                float v1 = fmaxf((acc[nt][3] - mB) * rBi * g2s[c + 1] + be2s[c + 1], 0.f);
                atomicAdd(&g_flow[(size_t)rB * 256 + off_n + c],     v0);
                atomicAdd(&g_flow[(size_t)rB * 256 + off_n + c + 1], v1);
            }
        }
        __syncthreads();
    }
}

// ---------------- node finalize ----------------
#define FINAL_SMEM_FLOATS (49920 + 4 * 1568)
__global__ void __launch_bounds__(512, 1) k_final(
    const float* __restrict__ x,
    const float* __restrict__ node_w, const float* __restrict__ node_b,
    const float* __restrict__ node_g, const float* __restrict__ node_be,
    const float* __restrict__ self_w, const float* __restrict__ self_b,
    const float* __restrict__ self_g, const float* __restrict__ self_be,
    float* __restrict__ out)
{
    extern __shared__ unsigned char smraw[];
    float* sm = (float*)smraw;
    float* nw = sm;
    float* sw = sm + 32768;
    float* nbv  = sm + 49152;
    float* ngv  = sm + 49280;
    float* nbev = sm + 49408;
    float* sbv  = sm + 49536;
    float* sgv  = sm + 49664;
    float* sbev = sm + 49792;
    for (int idx = threadIdx.x; idx < 32768; idx += 512) nw[idx] = node_w[idx];
    for (int idx = threadIdx.x; idx < 16384; idx += 512) sw[idx] = self_w[idx];
    if (threadIdx.x < 128) {
        int i = threadIdx.x;
        nbv[i] = node_b[i]; ngv[i] = node_g[i]; nbev[i] = node_be[i];
        sbv[i] = self_b[i]; sgv[i] = self_g[i]; sbev[i] = self_be[i];
    }
    __syncthreads();
    int unit = threadIdx.x >> 7;
    int t    = threadIdx.x & 127;
    int wu   = t >> 5;
    int lane = threadIdx.x & 31;
    int barid = unit + 1;
    float* U     = sm + 49920 + unit * 1568;
    float* flows = U;
    float* xns   = U + 1024;
    float* red   = U + 1536;
    int nG = (N_NODES + 3) >> 2;
    int gu = blockIdx.x * 4 + unit;
    int stride = gridDim.x * 4;
    for (int g = gu; g < nG; g += stride) {
        int base = g * 4;
        int nodes[4];
        bool valid[4];
        #pragma unroll
        for (int s = 0; s < 4; s++) {
            int n = base + s;
            valid[s] = n < N_NODES;
            nodes[s] = valid[s] ? n : 0;
        }
        #pragma unroll
        for (int pass = 0; pass < 8; pass++) {
            int idx = t + pass * 128;
            int s = idx >> 8, j = idx & 255;
            flows[j * 4 + s] = g_flow[(size_t)nodes[s] * 256 + j];
        }
        #pragma unroll
        for (int pass = 0; pass < 4; pass++) {
            int idx = t + pass * 128;
            int s = idx >> 7, i = idx & 127;
            xns[i * 4 + s] = x[(size_t)nodes[s] * XW + i];
        }
        barSync(barid);
        float u0 = 0, u1 = 0, u2 = 0, u3 = 0;
        #pragma unroll 8
        for (int j = 0; j < 256; j++) {
            float4 fv = *reinterpret_cast<float4*>(&flows[j * 4]);
            float wv = nw[j * 128 + t];
            u0 += fv.x * wv; u1 += fv.y * wv; u2 += fv.z * wv; u3 += fv.w * wv;
        }
        float v0 = 0, v1 = 0, v2 = 0, v3 = 0;
        #pragma unroll 8
        for (int i = 0; i < 128; i++) {
            float4 xv = *reinterpret_cast<float4*>(&xns[i * 4]);
            float wv = sw[i * 128 + t];
            v0 += xv.x * wv; v1 += xv.y * wv; v2 += xv.z * wv; v3 += xv.w * wv;
        }
        float nb_ = nbv[t], sb_ = sbv[t];
        float uu[4] = { u0 + nb_, u1 + nb_, u2 + nb_, u3 + nb_ };
        float vv[4] = { v0 + sb_, v1 + sb_, v2 + sb_, v3 + sb_ };
        float sums[8] = { uu[0], uu[1], uu[2], uu[3], vv[0], vv[1], vv[2], vv[3] };
        ureduce<8>(sums, red, wu, lane, barid);
        float du[4], dv[4], sq[8];
        #pragma unroll
        for (int s = 0; s < 4; s++) {
            du[s] = uu[s] - sums[s] * (1.f / 128.f);
            dv[s] = vv[s] - sums[4 + s] * (1.f / 128.f);
            sq[s] = du[s] * du[s];
            sq[4 + s] = dv[s] * dv[s];
        }
        ureduce<8>(sq, red, wu, lane, barid);
        float ng_ = ngv[t], nbe_ = nbev[t], sg_ = sgv[t], sbe_ = sbev[t];
        #pragma unroll
        for (int s = 0; s < 4; s++) {
            float r1 = fmaxf(du[s] * rsqrtf(sq[s] * (1.f / 128.f) + LN_EPS) * ng_ + nbe_, 0.f);
            float r2 = fmaxf(dv[s] * rsqrtf(sq[4 + s] * (1.f / 128.f) + LN_EPS) * sg_ + sbe_, 0.f);
            if (valid[s]) out[(size_t)nodes[s] * XW + t] = r1 + r2;
        }
        if (t < 32) {
            #pragma unroll
            for (int s = 0; s < 4; s++)
                if (valid[s])
                    out[(size_t)nodes[s] * XW + 128 + t] = x[(size_t)nodes[s] * XW + 128 + t];
        }
    }
}

extern "C" void kernel_launch(void* const* d_in, const int* in_sizes, int n_in,
                              void* d_out, int out_size) {
    const float* x      = (const float*)d_in[0];
    const int*   ei     = (const int*)d_in[1];
    const float* eattr  = (const float*)d_in[2];
    const float* w_att  = (const float*)d_in[3];
    const float* b_att  = (const float*)d_in[4];
    const float* d2t_w1 = (const float*)d_in[5];
    const float* d2t_b1 = (const float*)d_in[6];
    const float* d2t_g1 = (const float*)d_in[7];
    const float* d2t_be1= (const float*)d_in[8];
    const float* d2t_w2 = (const float*)d_in[9];
    const float* d2t_b2 = (const float*)d_in[10];
    const float* d2t_g2 = (const float*)d_in[11];
    const float* d2t_be2= (const float*)d_in[12];
    const float* t2d_w1 = (const float*)d_in[13];
    const float* t2d_b1 = (const float*)d_in[14];
    const float* t2d_g1 = (const float*)d_in[15];
    const float* t2d_be1= (const float*)d_in[16];
    const float* t2d_w2 = (const float*)d_in[17];
    const float* t2d_b2 = (const float*)d_in[18];
    const float* t2d_g2 = (const float*)d_in[19];
    const float* t2d_be2= (const float*)d_in[20];
    const float* node_w = (const float*)d_in[21];
    const float* node_b = (const float*)d_in[22];
    const float* node_g = (const float*)d_in[23];
    const float* node_be= (const float*)d_in[24];
    const float* self_w = (const float*)d_in[25];
    const float* self_b = (const float*)d_in[26];
    const float* self_g = (const float*)d_in[27];
    const float* self_be= (const float*)d_in[28];
    float* out = (float*)d_out;

    const int FINAL_SMEM_BYTES = FINAL_SMEM_FLOATS * 4;
    cudaFuncSetAttribute(k_node_mma, cudaFuncAttributeMaxDynamicSharedMemorySize, SMEM_NM);
    cudaFuncSetAttribute(k_edge_g1,  cudaFuncAttributeMaxDynamicSharedMemorySize, SMEM_G1);
    cudaFuncSetAttribute(k_edge_g2,  cudaFuncAttributeMaxDynamicSharedMemorySize, SMEM_G2);
    cudaFuncSetAttribute(k_final,    cudaFuncAttributeMaxDynamicSharedMemorySize, FINAL_SMEM_BYTES);

    int initThreads = (int)((size_t)N_NODES * 256 / 4);
    k_init_att<<<(initThreads + 255) / 256, 256>>>(x, w_att);
    k_node_mma<<<148, 256, SMEM_NM>>>(x, d2t_w1, t2d_w1);
    k_sumexp<<<(N_EDGES + 255) / 256, 256>>>(ei, b_att);
    k_edge_g1<<<296, 256, SMEM_G1>>>(0, ei, eattr, d2t_w1, d2t_b1, d2t_g1, d2t_be1);
    k_edge_g1<<<296, 256, SMEM_G1>>>(1, ei, eattr, t2d_w1, t2d_b1, t2d_be1 ? t2d_g1 : t2d_g1, t2d_be1);
    k_edge_g2<<<148, 512, SMEM_G2>>>(0, ei, d2t_w2, d2t_b2, d2t_g2, d2t_be2);
    k_edge_g2<<<148, 512, SMEM_G2>>>(1, ei, t2d_w2, t2d_b2, t2d_g2, t2d_be2);
    k_final<<<148, 512, FINAL_SMEM_BYTES>>>(x,
        node_w, node_b, node_g, node_be,
        self_w, self_b, self_g, self_be, out);
}

// round 7
// speedup vs baseline: 3.1023x; 1.2530x over previous
#include <cuda_runtime.h>
#include <cuda_bf16.h>
#include <math.h>
#include <stdint.h>

#define N_NODES 50000
#define N_EDGES 400000
#define D 128
#define H 256
#define EATTR 64
#define XW 160
#define LN_EPS 1e-5f
#define SLOPE 0.01f
#define MAXT 6252

__device__ float g_P0[(size_t)N_NODES * H];
__device__ float g_P1[(size_t)N_NODES * H];
__device__ float g_acol[N_NODES];
__device__ float g_arow[N_NODES];
__device__ float g_expv[N_EDGES];
__device__ int   g_elist0[N_EDGES];
__device__ int   g_elist1[N_EDGES];
__device__ float g_flow[(size_t)N_NODES * 256];
__device__ float g_U[(size_t)N_NODES * 128];
__device__ uint4 g_hf4[(size_t)2 * MAXT * 4096];
__device__ float g_dirsum[2];
__device__ int   g_ecnt[2];

__device__ __forceinline__ void split2(float v0, float v1, uint32_t& hi, uint32_t& lo) {
    __nv_bfloat16 h0 = __float2bfloat16(v0), h1 = __float2bfloat16(v1);
    __nv_bfloat16 l0 = __float2bfloat16(v0 - __bfloat162float(h0));
    __nv_bfloat16 l1 = __float2bfloat16(v1 - __bfloat162float(h1));
    hi = ((uint32_t)__bfloat16_as_ushort(h1) << 16) | __bfloat16_as_ushort(h0);
    lo = ((uint32_t)__bfloat16_as_ushort(l1) << 16) | __bfloat16_as_ushort(l0);
}

__device__ __forceinline__ void mma_bf16(float* c, const uint4& a, const uint2& b) {
    asm volatile(
        "mma.sync.aligned.m16n8k16.row.col.f32.bf16.bf16.f32 "
        "{%0,%1,%2,%3}, {%4,%5,%6,%7}, {%8,%9}, {%0,%1,%2,%3};\n"
        : "+f"(c[0]), "+f"(c[1]), "+f"(c[2]), "+f"(c[3])
        : "r"(a.x), "r"(a.y), "r"(a.z), "r"(a.w), "r"(b.x), "r"(b.y));
}

// ---------------- prologue ----------------
__global__ void k_init_att(const float* __restrict__ x, const float* __restrict__ w_att) {
    size_t i = (size_t)blockIdx.x * blockDim.x + threadIdx.x;
    size_t n4 = (size_t)N_NODES * 256 / 4;
    if (i < n4) reinterpret_cast<float4*>(g_flow)[i] = make_float4(0.f, 0.f, 0.f, 0.f);
    if (i == 0) { g_dirsum[0] = 0.f; g_dirsum[1] = 0.f; g_ecnt[0] = 0; g_ecnt[1] = 0; }
    int gw = (int)(i >> 5);
    int lane = threadIdx.x & 31;
    if (gw < N_NODES) {
        const float* xr = x + (size_t)gw * XW;
        float s0 = 0.f, s1 = 0.f;
        #pragma unroll
        for (int k = lane; k < 128; k += 32) {
            float v = xr[k];
            s0 += v * w_att[k]; s1 += v * w_att[128 + k];
        }
        #pragma unroll
        for (int o = 16; o; o >>= 1) {
            s0 += __shfl_xor_sync(0xffffffffu, s0, o);
            s1 += __shfl_xor_sync(0xffffffffu, s1, o);
        }
        if (lane == 0) { g_acol[gw] = s0; g_arow[gw] = s1; }
    }
}

__global__ void k_sumexp(const int* __restrict__ ei, const float* __restrict__ b_att) {
    __shared__ int c0, c1, base0, base1;
    __shared__ float rs0[8], rs1[8];
    if (threadIdx.x == 0) { c0 = 0; c1 = 0; }
    __syncthreads();
    int e = blockIdx.x * blockDim.x + threadIdx.x;
    int dir = -1, pos = 0;
    float ex = 0.f;
    if (e < N_EDGES) {
        int r = ei[e], c = ei[N_EDGES + e];
        if (r < c) dir = 0; else if (r > c) dir = 1;
        if (dir >= 0) {
            float z = g_acol[c] + g_arow[r] + b_att[0];
            float lg = z > 0.f ? z : SLOPE * z;
            ex = expf(lg);
            pos = atomicAdd(dir ? &c1 : &c0, 1);
        }
        g_expv[e] = ex;
    }
    float v0 = (dir == 0) ? ex : 0.f;
    float v1 = (dir == 1) ? ex : 0.f;
    #pragma unroll
    for (int o = 16; o; o >>= 1) {
        v0 += __shfl_xor_sync(0xffffffffu, v0, o);
        v1 += __shfl_xor_sync(0xffffffffu, v1, o);
    }
    int w = threadIdx.x >> 5, l = threadIdx.x & 31;
    if (l == 0) { rs0[w] = v0; rs1[w] = v1; }
    __syncthreads();
    if (threadIdx.x == 0) {
        float t0 = 0.f, t1 = 0.f;
        for (int k = 0; k < 8; k++) { t0 += rs0[k]; t1 += rs1[k]; }
        if (t0 != 0.f) atomicAdd(&g_dirsum[0], t0);
        if (t1 != 0.f) atomicAdd(&g_dirsum[1], t1);
        base0 = c0 ? atomicAdd(&g_ecnt[0], c0) : 0;
        base1 = c1 ? atomicAdd(&g_ecnt[1], c1) : 0;
    }
    __syncthreads();
    if (dir == 0) g_elist0[base0 + pos] = e;
    else if (dir == 1) g_elist1[base1 + pos] = e;
}

// ---------------- node precompute P = xn @ W1top (dir per CTA) ----------------
#define NM_AH 0
#define NM_AL 16384
#define NM_WH 32768
#define NM_WL 98304
#define SMEM_NM 163840

__global__ void __launch_bounds__(256, 1) k_node_mma(
    const float* __restrict__ x, const float* __restrict__ w0, const float* __restrict__ w1)
{
    extern __shared__ unsigned char sm[];
    int tid = threadIdx.x;
    int lane = tid & 31, wid = tid >> 5;
    int slot = wid & 3, nh = wid >> 2;
    int gid = lane >> 2, tig = lane & 3;
    int d  = blockIdx.x / 148;
    int b0 = blockIdx.x % 148;

    const float* W = d ? w1 : w0;
    float* P = d ? g_P1 : g_P0;
    for (int idx = tid; idx < 16384; idx += 256) {
        int k2i = idx >> 8, n = idx & 255;
        int k = 2 * k2i;
        float v0 = W[(size_t)k * H + n], v1 = W[(size_t)(k + 1) * H + n];
        uint32_t hi, lo; split2(v0, v1, hi, lo);
        int gn = n >> 3, ks = k >> 4;
        int lane_t = (n & 7) * 4 + ((k & 7) >> 1);
        int reg = (k & 15) >> 3;
        uint32_t off = ((uint32_t)(gn * 8 + ks) * 32 + lane_t) * 8 + reg * 4;
        *(uint32_t*)(sm + NM_WH + off) = hi;
        *(uint32_t*)(sm + NM_WL + off) = lo;
    }
    __syncthreads();
    int nTn = (N_NODES + 63) >> 6;
    for (int tile = b0; tile < nTn; tile += 148) {
        #pragma unroll
        for (int j = 0; j < 8; j++) {
            int r = wid * 8 + j;
            int node = tile * 64 + r;
            int nodeC = node < N_NODES ? node : 0;
            int jr = r & 15, sl = r >> 4;
            #pragma unroll
            for (int kh = 0; kh < 2; kh++) {
                float2 v = *(const float2*)(x + (size_t)nodeC * XW + kh * 64 + 2 * lane);
                uint32_t hi, lo; split2(v.x, v.y, hi, lo);
                int lane_t = (jr & 7) * 4 + (lane & 3);
                int reg = (jr >> 3) | (((lane >> 2) & 1) << 1);
                int ks = kh * 4 + (lane >> 3);
                uint32_t off = ((uint32_t)(sl * 8 + ks) * 32 + lane_t) * 16 + reg * 4;
                *(uint32_t*)(sm + NM_AH + off) = hi;
                *(uint32_t*)(sm + NM_AL + off) = lo;
            }
        }
        __syncthreads();
        float acc[16][4];
        #pragma unroll
        for (int nt = 0; nt < 16; nt++)
            #pragma unroll
            for (int q = 0; q < 4; q++) acc[nt][q] = 0.f;
        #pragma unroll
        for (int ks = 0; ks < 8; ks++) {
            uint4 ah = *(const uint4*)(sm + NM_AH + ((uint32_t)(slot * 8 + ks) * 32 + lane) * 16);
            uint4 al = *(const uint4*)(sm + NM_AL + ((uint32_t)(slot * 8 + ks) * 32 + lane) * 16);
            #pragma unroll
            for (int nt = 0; nt < 16; nt++) {
                int gn = nh * 16 + nt;
                uint2 bh = *(const uint2*)(sm + NM_WH + ((uint32_t)(gn * 8 + ks) * 32 + lane) * 8);
                uint2 bl = *(const uint2*)(sm + NM_WL + ((uint32_t)(gn * 8 + ks) * 32 + lane) * 8);
                mma_bf16(acc[nt], ah, bh);
                mma_bf16(acc[nt], al, bh);
                mma_bf16(acc[nt], ah, bl);
            }
        }
        int r0 = slot * 16 + gid, r1 = r0 + 8;
        int n0 = tile * 64 + r0, n1 = tile * 64 + r1;
        #pragma unroll
        for (int nt = 0; nt < 16; nt++) {
            int c = nh * 128 + nt * 8 + tig * 2;
            if (n0 < N_NODES) *(float2*)(P + (size_t)n0 * H + c) = make_float2(acc[nt][0], acc[nt][1]);
            if (n1 < N_NODES) *(float2*)(P + (size_t)n1 * H + c) = make_float2(acc[nt][2], acc[nt][3]);
        }
        __syncthreads();
    }
}

// ---------------- k_edge_g1 (both dirs in one launch) ----------------
#define G1_EID   0
#define G1_COL   256
#define G1_ATT   512
#define G1_ST    768
#define G1_B1    1792
#define G1_G1    2816
#define G1_BE1   3840
#define G1_A1H   4864
#define G1_A1L   13056
#define G1_W1H   21248
#define G1_W1L   54016
#define SMEM_G1  86784

__global__ void __launch_bounds__(256, 2) k_edge_g1(
    const int* __restrict__ ei, const float* __restrict__ eattr,
    const float* __restrict__ w1a, const float* __restrict__ b1a,
    const float* __restrict__ g1va, const float* __restrict__ be1va,
    const float* __restrict__ w1b, const float* __restrict__ b1b,
    const float* __restrict__ g1vb, const float* __restrict__ be1vb)
{
    extern __shared__ unsigned char sm[];
    int*   eidm  = (int*)(sm + G1_EID);
    int*   colm  = (int*)(sm + G1_COL);
    float* attnm = (float*)(sm + G1_ATT);
    float* statm = (float*)(sm + G1_ST);
    float* b1s   = (float*)(sm + G1_B1);
    float* g1s   = (float*)(sm + G1_G1);
    float* be1s  = (float*)(sm + G1_BE1);

    int tid = threadIdx.x;
    int lane = tid & 31, wid = tid >> 5;
    int slot = wid & 3, half = wid >> 2;
    int gid = lane >> 2, tig = lane & 3;
    int dir = blockIdx.x / 296;
    int b0  = blockIdx.x % 296;

    const float* w1full = dir ? w1b : w1a;
    const float* b1v  = dir ? b1b : b1a;
    const float* g1v  = dir ? g1vb : g1va;
    const float* be1v = dir ? be1vb : be1va;

    const float* wbg = w1full + 128 * H;
    for (int idx = tid; idx < 8192; idx += 256) {
        int k2i = idx >> 8, n = idx & 255;
        int k = 2 * k2i;
        float v0 = wbg[(size_t)k * H + n], v1 = wbg[(size_t)(k + 1) * H + n];
        uint32_t hi, lo; split2(v0, v1, hi, lo);
        int gn = n >> 3, ks = k >> 4;
        int lane_t = (n & 7) * 4 + ((k & 7) >> 1);
        int reg = (k & 15) >> 3;
        uint32_t off = ((uint32_t)(gn * 4 + ks) * 32 + lane_t) * 8 + reg * 4;
        *(uint32_t*)(sm + G1_W1H + off) = hi;
        *(uint32_t*)(sm + G1_W1L + off) = lo;
    }
    b1s[tid]  = b1v[tid];
    g1s[tid]  = g1v[tid];
    be1s[tid] = be1v[tid];

    const int*   elist = dir ? g_elist1 : g_elist0;
    const float* Pd    = dir ? g_P1 : g_P0;
    int   cnt = g_ecnt[dir];
    float inv = 1.f / g_dirsum[dir];
    int nT = (cnt + 63) >> 6;
    __syncthreads();

    for (int tile = b0; tile < nT; tile += 296) {
        if (tid < 64) {
            int li = tile * 64 + tid;
            bool valid = li < cnt;
            int ee = valid ? elist[li] : 0;
            eidm[tid]  = valid ? ee : -1;
            colm[tid]  = valid ? ei[N_EDGES + ee] : 0;
            attnm[tid] = valid ? g_expv[ee] * inv : 0.f;
        }
        __syncthreads();

        #pragma unroll
        for (int j = 0; j < 8; j++) {
            int r = wid * 8 + j;
            int e = eidm[r];
            int eC = e < 0 ? 0 : e;
            float2 v = *(const float2*)(eattr + (size_t)eC * EATTR + 2 * lane);
            uint32_t hi, lo; split2(v.x, v.y, hi, lo);
            int jr = r & 15;
            int lane_t = (jr & 7) * 4 + (lane & 3);
            int reg = (jr >> 3) | (((lane >> 2) & 1) << 1);
            int ks = lane >> 3;
            uint32_t off = ((uint32_t)((r >> 4) * 4 + ks) * 32 + lane_t) * 16 + reg * 4;
            *(uint32_t*)(sm + G1_A1H + off) = hi;
            *(uint32_t*)(sm + G1_A1L + off) = lo;
        }
        __syncthreads();

        float acc[16][4];
        #pragma unroll
        for (int nt = 0; nt < 16; nt++)
            #pragma unroll
            for (int q = 0; q < 4; q++) acc[nt][q] = 0.f;
        #pragma unroll
        for (int ks = 0; ks < 4; ks++) {
            uint4 ah = *(const uint4*)(sm + G1_A1H + ((uint32_t)(slot * 4 + ks) * 32 + lane) * 16);
            uint4 al = *(const uint4*)(sm + G1_A1L + ((uint32_t)(slot * 4 + ks) * 32 + lane) * 16);
            #pragma unroll
            for (int nt = 0; nt < 16; nt++) {
                int gn = half * 16 + nt;
                uint2 bh = *(const uint2*)(sm + G1_W1H + ((uint32_t)(gn * 4 + ks) * 32 + lane) * 8);
                uint2 bl = *(const uint2*)(sm + G1_W1L + ((uint32_t)(gn * 4 + ks) * 32 + lane) * 8);
                mma_bf16(acc[nt], ah, bh);
                mma_bf16(acc[nt], al, bh);
                mma_bf16(acc[nt], ah, bl);
            }
        }

        int r0 = slot * 16 + gid, r1 = r0 + 8;
        float at0 = attnm[r0], at1 = attnm[r1];
        const float* P0 = Pd + (size_t)colm[r0] * H;
        const float* P1 = Pd + (size_t)colm[r1] * H;
        float sA = 0.f, qA = 0.f, sB = 0.f, qB = 0.f;
        #pragma unroll
        for (int nt = 0; nt < 16; nt++) {
            int c = half * 128 + nt * 8 + tig * 2;
            float2 p0 = *(const float2*)(P0 + c);
            float2 p1 = *(const float2*)(P1 + c);
            float b10 = b1s[c], b11 = b1s[c + 1];
            acc[nt][0] = at0 * (p0.x + acc[nt][0]) + b10;
            acc[nt][1] = at0 * (p0.y + acc[nt][1]) + b11;
            acc[nt][2] = at1 * (p1.x + acc[nt][2]) + b10;
            acc[nt][3] = at1 * (p1.y + acc[nt][3]) + b11;
            sA += acc[nt][0] + acc[nt][1];
            qA += acc[nt][0] * acc[nt][0] + acc[nt][1] * acc[nt][1];
            sB += acc[nt][2] + acc[nt][3];
            qB += acc[nt][2] * acc[nt][2] + acc[nt][3] * acc[nt][3];
        }
        #pragma unroll
        for (int o = 1; o <= 2; o <<= 1) {
            sA += __shfl_xor_sync(0xffffffffu, sA, o);
            qA += __shfl_xor_sync(0xffffffffu, qA, o);
            sB += __shfl_xor_sync(0xffffffffu, sB, o);
            qB += __shfl_xor_sync(0xffffffffu, qB, o);
        }
        if (tig == 0) {
            statm[(r0 * 2 + half) * 2]     = sA;
            statm[(r0 * 2 + half) * 2 + 1] = qA;
            statm[(r1 * 2 + half) * 2]     = sB;
            statm[(r1 * 2 + half) * 2 + 1] = qB;
        }
        __syncthreads();
        float sTA = sA + statm[(r0 * 2 + (half ^ 1)) * 2];
        float qTA = qA + statm[(r0 * 2 + (half ^ 1)) * 2 + 1];
        float sTB = sB + statm[(r1 * 2 + (half ^ 1)) * 2];
        float qTB = qB + statm[(r1 * 2 + (half ^ 1)) * 2 + 1];
        float mA = sTA * (1.f / 256.f);
        float rA = rsqrtf(fmaxf(qTA * (1.f / 256.f) - mA * mA, 0.f) + LN_EPS);
        float mB = sTB * (1.f / 256.f);
        float rB = rsqrtf(fmaxf(qTB * (1.f / 256.f) - mB * mB, 0.f) + LN_EPS);

        uint2* hf2 = (uint2*)(g_hf4 + (size_t)(dir * MAXT + tile) * 4096);
        #pragma unroll
        for (int nt = 0; nt < 16; nt++) {
            int c = half * 128 + nt * 8 + tig * 2;
            float u0 = fmaxf((acc[nt][0] - mA) * rA * g1s[c]     + be1s[c],     0.f);
            float u1 = fmaxf((acc[nt][1] - mA) * rA * g1s[c + 1] + be1s[c + 1], 0.f);
            float w0 = fmaxf((acc[nt][2] - mB) * rB * g1s[c]     + be1s[c],     0.f);
            float w1 = fmaxf((acc[nt][3] - mB) * rB * g1s[c + 1] + be1s[c + 1], 0.f);
            uint32_t hiA, loA, hiB, loB;
            split2(u0, u1, hiA, loA);
            split2(w0, w1, hiB, loB);
            int ks = half * 8 + (nt >> 1);
            uint32_t g = (uint32_t)(slot * 16 + ks) * 32 + lane;
            hf2[g * 2 + (nt & 1)]        = make_uint2(hiA, hiB);
            hf2[4096 + g * 2 + (nt & 1)] = make_uint2(loA, loB);
        }
        __syncthreads();
    }
}

// ---------------- k_edge_g2 (both dirs in one launch) ----------------
#define G2_ST    0
#define G2_B2    2048
#define G2_G2    2560
#define G2_BE2   3072
#define G2_W2H   3584
#define G2_W2L   69120
#define SMEM_G2  134656

__global__ void __launch_bounds__(512, 1) k_edge_g2(
    const int* __restrict__ ei,
    const float* __restrict__ w2a, const float* __restrict__ b2a,
    const float* __restrict__ g2va, const float* __restrict__ be2va,
    const float* __restrict__ w2b, const float* __restrict__ b2b,
    const float* __restrict__ g2vb, const float* __restrict__ be2vb)
{
    extern __shared__ unsigned char sm[];
    float* statm = (float*)(sm + G2_ST);
    float* b2s   = (float*)(sm + G2_B2);
    float* g2s   = (float*)(sm + G2_G2);
    float* be2s  = (float*)(sm + G2_BE2);

    int tid = threadIdx.x;
    int lane = tid & 31, wid = tid >> 5;
    int slot = wid & 3, nh = wid >> 2;
    int gid = lane >> 2, tig = lane & 3;
    int dir = blockIdx.x / 148;
    int b0  = blockIdx.x % 148;

    const float* w2  = dir ? w2b : w2a;
    const float* b2  = dir ? b2b : b2a;
    const float* g2v = dir ? g2vb : g2va;
    const float* be2v= dir ? be2vb : be2va;

    for (int idx = tid; idx < 16384; idx += 512) {
        int k2i = idx >> 7, n = idx & 127;
        int k = 2 * k2i;
        float v0 = w2[(size_t)k * 128 + n], v1 = w2[(size_t)(k + 1) * 128 + n];
        uint32_t hi, lo; split2(v0, v1, hi, lo);
        int gn = n >> 3, ks = k >> 4;
        int lane_t = (n & 7) * 4 + ((k & 7) >> 1);
        int reg = (k & 15) >> 3;
        uint32_t off = ((uint32_t)(gn * 16 + ks) * 32 + lane_t) * 8 + reg * 4;
        *(uint32_t*)(sm + G2_W2H + off) = hi;
        *(uint32_t*)(sm + G2_W2L + off) = lo;
    }
    if (tid < 128) { b2s[tid] = b2[tid]; g2s[tid] = g2v[tid]; be2s[tid] = be2v[tid]; }

    const int* elist = dir ? g_elist1 : g_elist0;
    int cnt = g_ecnt[dir];
    int off_n = dir ? 0 : 128;
    int nT = (cnt + 63) >> 6;
    __syncthreads();

    for (int tile = b0; tile < nT; tile += 148) {
        int liA = tile * 64 + slot * 16 + gid;
        int liB = liA + 8;
        int rA = (liA < cnt) ? ei[elist[liA]] : -1;
        int rB = (liB < cnt) ? ei[elist[liB]] : -1;

        const uint4* hf4 = g_hf4 + (size_t)(dir * MAXT + tile) * 4096;
        float acc[4][4];
        #pragma unroll
        for (int nt = 0; nt < 4; nt++)
            #pragma unroll
            for (int q = 0; q < 4; q++) acc[nt][q] = 0.f;
        #pragma unroll
        for (int ks = 0; ks < 16; ks++) {
            uint32_t g = (uint32_t)(slot * 16 + ks) * 32 + lane;
            uint4 ah = hf4[g];
            uint4 al = hf4[2048 + g];
            #pragma unroll
            for (int nt = 0; nt < 4; nt++) {
                int gn = nh * 4 + nt;
                uint2 bh = *(const uint2*)(sm + G2_W2H + ((uint32_t)(gn * 16 + ks) * 32 + lane) * 8);
                uint2 bl = *(const uint2*)(sm + G2_W2L + ((uint32_t)(gn * 16 + ks) * 32 + lane) * 8);
                mma_bf16(acc[nt], ah, bh);
                mma_bf16(acc[nt], al, bh);
                mma_bf16(acc[nt], ah, bl);
            }
        }

        float sA = 0.f, qA = 0.f, sB = 0.f, qB = 0.f;
        #pragma unroll
        for (int nt = 0; nt < 4; nt++) {
            int c = nh * 32 + nt * 8 + tig * 2;
            acc[nt][0] += b2s[c];   acc[nt][1] += b2s[c + 1];
            acc[nt][2] += b2s[c];   acc[nt][3] += b2s[c + 1];
            sA += acc[nt][0] + acc[nt][1];
            qA += acc[nt][0] * acc[nt][0] + acc[nt][1] * acc[nt][1];
            sB += acc[nt][2] + acc[nt][3];
            qB += acc[nt][2] * acc[nt][2] + acc[nt][3] * acc[nt][3];
        }
        #pragma unroll
        for (int o = 1; o <= 2; o <<= 1) {
            sA += __shfl_xor_sync(0xffffffffu, sA, o);
            qA += __shfl_xor_sync(0xffffffffu, qA, o);
            sB += __shfl_xor_sync(0xffffffffu, sB, o);
            qB += __shfl_xor_sync(0xffffffffu, qB, o);
        }
        int e0 = slot * 16 + gid, e1 = e0 + 8;
        if (tig == 0) {
            statm[(e0 * 4 + nh) * 2]     = sA;
            statm[(e0 * 4 + nh) * 2 + 1] = qA;
            statm[(e1 * 4 + nh) * 2]     = sB;
            statm[(e1 * 4 + nh) * 2 + 1] = qB;
        }
        __syncthreads();
        float sTA = 0.f, qTA = 0.f, sTB = 0.f, qTB = 0.f;
        #pragma unroll
        for (int h = 0; h < 4; h++) {
            sTA += statm[(e0 * 4 + h) * 2];  qTA += statm[(e0 * 4 + h) * 2 + 1];
            sTB += statm[(e1 * 4 + h) * 2];  qTB += statm[(e1 * 4 + h) * 2 + 1];
        }
        float mA = sTA * (1.f / 128.f);
        float rAi = rsqrtf(fmaxf(qTA * (1.f / 128.f) - mA * mA, 0.f) + LN_EPS);
        float mB = sTB * (1.f / 128.f);
        float rBi = rsqrtf(fmaxf(qTB * (1.f / 128.f) - mB * mB, 0.f) + LN_EPS);
        #pragma unroll
        for (int nt = 0; nt < 4; nt++) {
            int c = nh * 32 + nt * 8 + tig * 2;
            if (rA >= 0) {
                float v0 = fmaxf((acc[nt][0] - mA) * rAi * g2s[c]     + be2s[c],     0.f);
                float v1 = fmaxf((acc[nt][1] - mA) * rAi * g2s[c + 1] + be2s[c + 1], 0.f);
                atomicAdd(&g_flow[(size_t)rA * 256 + off_n + c],     v0);
                atomicAdd(&g_flow[(size_t)rA * 256 + off_n + c + 1], v1);
            }
            if (rB >= 0) {
                float v0 = fmaxf((acc[nt][2] - mB) * rBi * g2s[c]     + be2s[c],     0.f);
                float v1 = fmaxf((acc[nt][3] - mB) * rBi * g2s[c + 1] + be2s[c + 1], 0.f);
                atomicAdd(&g_flow[(size_t)rB * 256 + off_n + c],     v0);
                atomicAdd(&g_flow[(size_t)rB * 256 + off_n + c + 1], v1);
            }
        }
        __syncthreads();
    }
}

// ---------------- k_final_a: U = relu(LN(flow @ node_w + b)) -> g_U ----------------
#define FA_ST  0
#define FA_NB  2048
#define FA_NG  2560
#define FA_NBE 3072
#define FA_AH  3584
#define FA_AL  36352
#define FA_WH  69120
#define FA_WL  134656
#define SMEM_FA 200192

__global__ void __launch_bounds__(512, 1) k_final_a(
    const float* __restrict__ node_w, const float* __restrict__ node_b,
    const float* __restrict__ node_g, const float* __restrict__ node_be)
{
    extern __shared__ unsigned char sm[];
    float* statm = (float*)(sm + FA_ST);
    float* nbs   = (float*)(sm + FA_NB);
    float* ngs   = (float*)(sm + FA_NG);
    float* nbes  = (float*)(sm + FA_NBE);

    int tid = threadIdx.x;
    int lane = tid & 31, wid = tid >> 5;
    int slot = wid & 3, nh = wid >> 2;
    int gid = lane >> 2, tig = lane & 3;

    for (int idx = tid; idx < 16384; idx += 512) {
        int k2i = idx >> 7, n = idx & 127;
        int k = 2 * k2i;
        float v0 = node_w[(size_t)k * 128 + n], v1 = node_w[(size_t)(k + 1) * 128 + n];
        uint32_t hi, lo; split2(v0, v1, hi, lo);
        int gn = n >> 3, ks = k >> 4;
        int lane_t = (n & 7) * 4 + ((k & 7) >> 1);
        int reg = (k & 15) >> 3;
        uint32_t off = ((uint32_t)(gn * 16 + ks) * 32 + lane_t) * 8 + reg * 4;
        *(uint32_t*)(sm + FA_WH + off) = hi;
        *(uint32_t*)(sm + FA_WL + off) = lo;
    }
    if (tid < 128) { nbs[tid] = node_b[tid]; ngs[tid] = node_g[tid]; nbes[tid] = node_be[tid]; }
    __syncthreads();

    int nTn = (N_NODES + 63) >> 6;
    for (int tile = blockIdx.x; tile < nTn; tile += gridDim.x) {
        // stage A = flow rows (4 rows per warp, K=256)
        #pragma unroll
        for (int j = 0; j < 4; j++) {
            int r = wid * 4 + j;
            int node = tile * 64 + r;
            int nodeC = node < N_NODES ? node : 0;
            int jr = r & 15, sl = r >> 4;
            #pragma unroll
            for (int kh = 0; kh < 4; kh++) {
                float2 v = *(const float2*)(g_flow + (size_t)nodeC * 256 + kh * 64 + 2 * lane);
                uint32_t hi, lo; split2(v.x, v.y, hi, lo);
                int lane_t = (jr & 7) * 4 + (lane & 3);
                int reg = (jr >> 3) | (((lane >> 2) & 1) << 1);
                int ks = kh * 4 + (lane >> 3);
                uint32_t off = ((uint32_t)(sl * 16 + ks) * 32 + lane_t) * 16 + reg * 4;
                *(uint32_t*)(sm + FA_AH + off) = hi;
                *(uint32_t*)(sm + FA_AL + off) = lo;
            }
        }
        __syncthreads();

        float acc[4][4];
        #pragma unroll
        for (int nt = 0; nt < 4; nt++)
            #pragma unroll
            for (int q = 0; q < 4; q++) acc[nt][q] = 0.f;
        #pragma unroll
        for (int ks = 0; ks < 16; ks++) {
            uint4 ah = *(const uint4*)(sm + FA_AH + ((uint32_t)(slot * 16 + ks) * 32 + lane) * 16);
            uint4 al = *(const uint4*)(sm + FA_AL + ((uint32_t)(slot * 16 + ks) * 32 + lane) * 16);
            #pragma unroll
            for (int nt = 0; nt < 4; nt++) {
                int gn = nh * 4 + nt;
                uint2 bh = *(const uint2*)(sm + FA_WH + ((uint32_t)(gn * 16 + ks) * 32 + lane) * 8);
                uint2 bl = *(const uint2*)(sm + FA_WL + ((uint32_t)(gn * 16 + ks) * 32 + lane) * 8);
                mma_bf16(acc[nt], ah, bh);
                mma_bf16(acc[nt], al, bh);
                mma_bf16(acc[nt], ah, bl);
            }
        }

        float sA = 0.f, qA = 0.f, sB = 0.f, qB = 0.f;
        #pragma unroll
        for (int nt = 0; nt < 4; nt++) {
            int c = nh * 32 + nt * 8 + tig * 2;
            acc[nt][0] += nbs[c];   acc[nt][1] += nbs[c + 1];
            acc[nt][2] += nbs[c];   acc[nt][3] += nbs[c + 1];
            sA += acc[nt][0] + acc[nt][1];
            qA += acc[nt][0] * acc[nt][0] + acc[nt][1] * acc[nt][1];
            sB += acc[nt][2] + acc[nt][3];
            qB += acc[nt][2] * acc[nt][2] + acc[nt][3] * acc[nt][3];
        }
        #pragma unroll
        for (int o = 1; o <= 2; o <<= 1) {
            sA += __shfl_xor_sync(0xffffffffu, sA, o);
            qA += __shfl_xor_sync(0xffffffffu, qA, o);
            sB += __shfl_xor_sync(0xffffffffu, sB, o);
            qB += __shfl_xor_sync(0xffffffffu, qB, o);
        }
        int e0 = slot * 16 + gid, e1 = e0 + 8;
        if (tig == 0) {
            statm[(e0 * 4 + nh) * 2]     = sA;
            statm[(e0 * 4 + nh) * 2 + 1] = qA;
            statm[(e1 * 4 + nh) * 2]     = sB;
            statm[(e1 * 4 + nh) * 2 + 1] = qB;
        }
        __syncthreads();
        float sTA = 0.f, qTA = 0.f, sTB = 0.f, qTB = 0.f;
        #pragma unroll
        for (int h = 0; h < 4; h++) {
            sTA += statm[(e0 * 4 + h) * 2];  qTA += statm[(e0 * 4 + h) * 2 + 1];
            sTB += statm[(e1 * 4 + h) * 2];  qTB += statm[(e1 * 4 + h) * 2 + 1];
        }
        float mA = sTA * (1.f / 128.f);
        float rAi = rsqrtf(fmaxf(qTA * (1.f / 128.f) - mA * mA, 0.f) + LN_EPS);
        float mB = sTB * (1.f / 128.f);
        float rBi = rsqrtf(fmaxf(qTB * (1.f / 128.f) - mB * mB, 0.f) + LN_EPS);
        int n0 = tile * 64 + e0, n1 = tile * 64 + e1;
        #pragma unroll
        for (int nt = 0; nt < 4; nt++) {
            int c = nh * 32 + nt * 8 + tig * 2;
            if (n0 < N_NODES) {
                float v0 = fmaxf((acc[nt][0] - mA) * rAi * ngs[c]     + nbes[c],     0.f);
                float v1 = fmaxf((acc[nt][1] - mA) * rAi * ngs[c + 1] + nbes[c + 1], 0.f);
                *(float2*)(g_U + (size_t)n0 * 128 + c) = make_float2(v0, v1);
            }
            if (n1 < N_NODES) {
                float v0 = fmaxf((acc[nt][2] - mB) * rBi * ngs[c]     + nbes[c],     0.f);
                float v1 = fmaxf((acc[nt][3] - mB) * rBi * ngs[c + 1] + nbes[c + 1], 0.f);
                *(float2*)(g_U + (size_t)n1 * 128 + c) = make_float2(v0, v1);
            }
        }
        __syncthreads();
    }
}

// ---------------- k_final_b: out = relu(LN(xn @ self_w + b)) + g_U  (+passthrough) ----------------
#define FB_ST  0
#define FB_SB  2048
#define FB_SG  2560
#define FB_SBE 3072
#define FB_AH  3584
#define FB_AL  19968
#define FB_WH  36352
#define FB_WL  69120
#define SMEM_FB 101888

__global__ void __launch_bounds__(512, 2) k_final_b(
    const float* __restrict__ x,
    const float* __restrict__ self_w, const float* __restrict__ self_b,
    const float* __restrict__ self_g, const float* __restrict__ self_be,
    float* __restrict__ out)
{
    extern __shared__ unsigned char sm[];
    float* statm = (float*)(sm + FB_ST);
    float* sbs   = (float*)(sm + FB_SB);
    float* sgs   = (float*)(sm + FB_SG);
    float* sbes  = (float*)(sm + FB_SBE);

    int tid = threadIdx.x;
    int lane = tid & 31, wid = tid >> 5;
    int slot = wid & 3, nh = wid >> 2;
    int gid = lane >> 2, tig = lane & 3;

    for (int idx = tid; idx < 8192; idx += 512) {
        int k2i = idx >> 7, n = idx & 127;
        int k = 2 * k2i;
        float v0 = self_w[(size_t)k * 128 + n], v1 = self_w[(size_t)(k + 1) * 128 + n];
        uint32_t hi, lo; split2(v0, v1, hi, lo);
        int gn = n >> 3, ks = k >> 4;
        int lane_t = (n & 7) * 4 + ((k & 7) >> 1);
        int reg = (k & 15) >> 3;
        uint32_t off = ((uint32_t)(gn * 8 + ks) * 32 + lane_t) * 8 + reg * 4;
        *(uint32_t*)(sm + FB_WH + off) = hi;
        *(uint32_t*)(sm + FB_WL + off) = lo;
    }
    if (tid < 128) { sbs[tid] = self_b[tid]; sgs[tid] = self_g[tid]; sbes[tid] = self_be[tid]; }
    __syncthreads();

    int nTn = (N_NODES + 63) >> 6;
    for (int tile = blockIdx.x; tile < nTn; tile += gridDim.x) {
        #pragma unroll
        for (int j = 0; j < 4; j++) {
            int r = wid * 4 + j;
            int node = tile * 64 + r;
            int nodeC = node < N_NODES ? node : 0;
            int jr = r & 15, sl = r >> 4;
            #pragma unroll
            for (int kh = 0; kh < 2; kh++) {
                float2 v = *(const float2*)(x + (size_t)nodeC * XW + kh * 64 + 2 * lane);
                uint32_t hi, lo; split2(v.x, v.y, hi, lo);
                int lane_t = (jr & 7) * 4 + (lane & 3);
                int reg = (jr >> 3) | (((lane >> 2) & 1) << 1);
                int ks = kh * 4 + (lane >> 3);
                uint32_t off = ((uint32_t)(sl * 8 + ks) * 32 + lane_t) * 16 + reg * 4;
                *(uint32_t*)(sm + FB_AH + off) = hi;
                *(uint32_t*)(sm + FB_AL + off) = lo;
            }
        }
        __syncthreads();

        float acc[4][4];
        #pragma unroll
        for (int nt = 0; nt < 4; nt++)
            #pragma unroll
            for (int q = 0; q < 4; q++) acc[nt][q] = 0.f;
        #pragma unroll
        for (int ks = 0; ks < 8; ks++) {
            uint4 ah = *(const uint4*)(sm + FB_AH + ((uint32_t)(slot * 8 + ks) * 32 + lane) * 16);
            uint4 al = *(const uint4*)(sm + FB_AL + ((uint32_t)(slot * 8 + ks) * 32 + lane) * 16);
            #pragma unroll
            for (int nt = 0; nt < 4; nt++) {
                int gn = nh * 4 + nt;
                uint2 bh = *(const uint2*)(sm + FB_WH + ((uint32_t)(gn * 8 + ks) * 32 + lane) * 8);
                uint2 bl = *(const uint2*)(sm + FB_WL + ((uint32_t)(gn * 8 + ks) * 32 + lane) * 8);
                mma_bf16(acc[nt], ah, bh);
                mma_bf16(acc[nt], al, bh);
                mma_bf16(acc[nt], ah, bl);
            }
        }

        float sA = 0.f, qA = 0.f, sB = 0.f, qB = 0.f;
        #pragma unroll
        for (int nt = 0; nt < 4; nt++) {
            int c = nh * 32 + nt * 8 + tig * 2;
            acc[nt][0] += sbs[c];   acc[nt][1] += sbs[c + 1];
            acc[nt][2] += sbs[c];   acc[nt][3] += sbs[c + 1];
            sA += acc[nt][0] + acc[nt][1];
            qA += acc[nt][0] * acc[nt][0] + acc[nt][1] * acc[nt][1];
            sB += acc[nt][2] + acc[nt][3];
            qB += acc[nt][2] * acc[nt][2] + acc[nt][3] * acc[nt][3];
        }
        #pragma unroll
        for (int o = 1; o <= 2; o <<= 1) {
            sA += __shfl_xor_sync(0xffffffffu, sA, o);
            qA += __shfl_xor_sync(0xffffffffu, qA, o);
            sB += __shfl_xor_sync(0xffffffffu, sB, o);
            qB += __shfl_xor_sync(0xffffffffu, qB, o);
        }
        int e0 = slot * 16 + gid, e1 = e0 + 8;
        if (tig == 0) {
            statm[(e0 * 4 + nh) * 2]     = sA;
            statm[(e0 * 4 + nh) * 2 + 1] = qA;
            statm[(e1 * 4 + nh) * 2]     = sB;
            statm[(e1 * 4 + nh) * 2 + 1] = qB;
        }
        __syncthreads();
        float sTA = 0.f, qTA = 0.f, sTB = 0.f, qTB = 0.f;
        #pragma unroll
        for (int h = 0; h < 4; h++) {
            sTA += statm[(e0 * 4 + h) * 2];  qTA += statm[(e0 * 4 + h) * 2 + 1];
            sTB += statm[(e1 * 4 + h) * 2];  qTB += statm[(e1 * 4 + h) * 2 + 1];
        }
        float mA = sTA * (1.f / 128.f);
        float rAi = rsqrtf(fmaxf(qTA * (1.f / 128.f) - mA * mA, 0.f) + LN_EPS);
        float mB = sTB * (1.f / 128.f);
        float rBi = rsqrtf(fmaxf(qTB * (1.f / 128.f) - mB * mB, 0.f) + LN_EPS);
        int n0 = tile * 64 + e0, n1 = tile * 64 + e1;
        #pragma unroll
        for (int nt = 0; nt < 4; nt++) {
            int c = nh * 32 + nt * 8 + tig * 2;
            if (n0 < N_NODES) {
                float2 uv = *(const float2*)(g_U + (size_t)n0 * 128 + c);
                float v0 = fmaxf((acc[nt][0] - mA) * rAi * sgs[c]     + sbes[c],     0.f) + uv.x;
                float v1 = fmaxf((acc[nt][1] - mA) * rAi * sgs[c + 1] + sbes[c + 1], 0.f) + uv.y;
                *(float2*)(out + (size_t)n0 * XW + c) = make_float2(v0, v1);
            }
            if (n1 < N_NODES) {
                float2 uv = *(const float2*)(g_U + (size_t)n1 * 128 + c);
                float v0 = fmaxf((acc[nt][2] - mB) * rBi * sgs[c]     + sbes[c],     0.f) + uv.x;
                float v1 = fmaxf((acc[nt][3] - mB) * rBi * sgs[c + 1] + sbes[c + 1], 0.f) + uv.y;
                *(float2*)(out + (size_t)n1 * XW + c) = make_float2(v0, v1);
            }
        }
        // split passthrough: cols 128..159
        for (int idx = tid; idx < 64 * 32; idx += 512) {
            int r = idx >> 5, j = idx & 31;
            int n = tile * 64 + r;
            if (n < N_NODES)
                out[(size_t)n * XW + 128 + j] = x[(size_t)n * XW + 128 + j];
        }
        __syncthreads();
    }
}

extern "C" void kernel_launch(void* const* d_in, const int* in_sizes, int n_in,
                              void* d_out, int out_size) {
    const float* x      = (const float*)d_in[0];
    const int*   ei     = (const int*)d_in[1];
    const float* eattr  = (const float*)d_in[2];
    const float* w_att  = (const float*)d_in[3];
    const float* b_att  = (const float*)d_in[4];
    const float* d2t_w1 = (const float*)d_in[5];
    const float* d2t_b1 = (const float*)d_in[6];
    const float* d2t_g1 = (const float*)d_in[7];
    const float* d2t_be1= (const float*)d_in[8];
    const float* d2t_w2 = (const float*)d_in[9];
    const float* d2t_b2 = (const float*)d_in[10];
    const float* d2t_g2 = (const float*)d_in[11];
    const float* d2t_be2= (const float*)d_in[12];
    const float* t2d_w1 = (const float*)d_in[13];
    const float* t2d_b1 = (const float*)d_in[14];
    const float* t2d_g1 = (const float*)d_in[15];
    const float* t2d_be1= (const float*)d_in[16];
    const float* t2d_w2 = (const float*)d_in[17];
    const float* t2d_b2 = (const float*)d_in[18];
    const float* t2d_g2 = (const float*)d_in[19];
    const float* t2d_be2= (const float*)d_in[20];
    const float* node_w = (const float*)d_in[21];
    const float* node_b = (const float*)d_in[22];
    const float* node_g = (const float*)d_in[23];
    const float* node_be= (const float*)d_in[24];
    const float* self_w = (const float*)d_in[25];
    const float* self_b = (const float*)d_in[26];
    const float* self_g = (const float*)d_in[27];
    const float* self_be= (const float*)d_in[28];
    float* out = (float*)d_out;

    cudaFuncSetAttribute(k_node_mma, cudaFuncAttributeMaxDynamicSharedMemorySize, SMEM_NM);
    cudaFuncSetAttribute(k_edge_g1,  cudaFuncAttributeMaxDynamicSharedMemorySize, SMEM_G1);
    cudaFuncSetAttribute(k_edge_g2,  cudaFuncAttributeMaxDynamicSharedMemorySize, SMEM_G2);
    cudaFuncSetAttribute(k_final_a,  cudaFuncAttributeMaxDynamicSharedMemorySize, SMEM_FA);
    cudaFuncSetAttribute(k_final_b,  cudaFuncAttributeMaxDynamicSharedMemorySize, SMEM_FB);

    int initThreads = (int)((size_t)N_NODES * 256 / 4);
    k_init_att<<<(initThreads + 255) / 256, 256>>>(x, w_att);
    k_node_mma<<<296, 256, SMEM_NM>>>(x, d2t_w1, t2d_w1);
    k_sumexp<<<(N_EDGES + 255) / 256, 256>>>(ei, b_att);
    k_edge_g1<<<592, 256, SMEM_G1>>>(ei, eattr,
        d2t_w1, d2t_b1, d2t_g1, d2t_be1,
        t2d_w1, t2d_b1, t2d_g1, t2d_be1);
    k_edge_g2<<<296, 512, SMEM_G2>>>(ei,
        d2t_w2, d2t_b2, d2t_g2, d2t_be2,
        t2d_w2, t2d_b2, t2d_g2, t2d_be2);
    k_final_a<<<148, 512, SMEM_FA>>>(node_w, node_b, node_g, node_be);
    k_final_b<<<296, 512, SMEM_FB>>>(x, self_w, self_b, self_g, self_be, out);
}